// round 10
// baseline (speedup 1.0000x reference)
#include <cuda_runtime.h>
#include <cstdint>
#include <math.h>

// Problem constants
#define Bc   8
#define Sc   1024
#define Dc   512
#define Hc   8
#define DKc  64

// Scratch (device globals; no allocations allowed)
__device__ float g_q[Bc * Hc * Sc * DKc];    // (B,H,S,64), pre-scaled by 1/8
__device__ float g_k[Bc * Hc * Sc * DKc];
__device__ float g_v[Bc * Hc * Sc * DKc];
__device__ float g_ctx[Bc * Sc * Dc];        // (B,S,512)

// ---------------------------------------------------------------------------
// SGEMM: out = X(M x 512) * W(512 x 512)^T + bias ; optional headed epilogue
// M=8192, N=512, K=512.  64x64 tile, 256 threads, 4x4 per thread.
// ---------------------------------------------------------------------------
template <int HEADED>
__global__ __launch_bounds__(256)
void sgemm_kernel(const float* __restrict__ X, const float* __restrict__ W,
                  const float* __restrict__ bias, float* __restrict__ out,
                  float scale)
{
    __shared__ __align__(16) float Ast[16][64];  // [k][m]
    __shared__ __align__(16) float Bst[16][64];  // [k][n]

    const int t  = threadIdx.x;
    const int tx = t & 15;
    const int ty = t >> 4;
    const int m0 = blockIdx.y * 64;
    const int n0 = blockIdx.x * 64;
    const int lr = t >> 2;         // 0..63
    const int lc = (t & 3) * 4;    // 0,4,8,12  (k-panel is 16 deep: full coverage)

    const float* Xp = X + (size_t)(m0 + lr) * 512 + lc;
    const float* Wp = W + (size_t)(n0 + lr) * 512 + lc;

    float acc[4][4] = {};

    for (int k0 = 0; k0 < 512; k0 += 16) {
        float4 av = *(const float4*)(Xp + k0);
        float4 wv = *(const float4*)(Wp + k0);
        __syncthreads();
        Ast[lc + 0][lr] = av.x; Ast[lc + 1][lr] = av.y;
        Ast[lc + 2][lr] = av.z; Ast[lc + 3][lr] = av.w;
        Bst[lc + 0][lr] = wv.x; Bst[lc + 1][lr] = wv.y;
        Bst[lc + 2][lr] = wv.z; Bst[lc + 3][lr] = wv.w;
        __syncthreads();
#pragma unroll
        for (int kk = 0; kk < 16; kk++) {
            float4 a = *(const float4*)&Ast[kk][ty * 4];
            float4 w = *(const float4*)&Bst[kk][tx * 4];
            float aa[4] = {a.x, a.y, a.z, a.w};
            float ww[4] = {w.x, w.y, w.z, w.w};
#pragma unroll
            for (int i = 0; i < 4; i++)
#pragma unroll
                for (int j = 0; j < 4; j++)
                    acc[i][j] += aa[i] * ww[j];
        }
    }

#pragma unroll
    for (int i = 0; i < 4; i++) {
        const int m = m0 + ty * 4 + i;
        float4 r;
        float* pr = (float*)&r;
#pragma unroll
        for (int j = 0; j < 4; j++) {
            const int o = n0 + tx * 4 + j;
            pr[j] = (acc[i][j] + bias[o]) * scale;
        }
        if (HEADED) {
            const int o0 = n0 + tx * 4;
            const int h = o0 >> 6, d = o0 & 63;
            const int b = m >> 10, s = m & 1023;
            *(float4*)(out + (((size_t)(b * Hc + h) * Sc + s) * DKc + d)) = r;
        } else {
            *(float4*)(out + (size_t)m * 512 + n0 + tx * 4) = r;
        }
    }
}

// ---------------------------------------------------------------------------
// Flash-style attention. One CTA = (b, h, 64 q-rows). 256 threads.
// Full 64x64 tile loads: 4 float4 per thread (R5 coverage fix).
// ---------------------------------------------------------------------------
__global__ __launch_bounds__(256)
void attn_kernel(const float* __restrict__ mIntoken,
                 const float* __restrict__ mInstat,
                 const float* __restrict__ mDataflow,
                 const unsigned char* __restrict__ mask)
{
    __shared__ __align__(16) float Qt[64][64];   // [d][qrow]
    __shared__ __align__(16) float KP[64][64];   // Kt: [d][krow]; then P: [qrow][kcol]
    __shared__ __align__(16) float Vs[64][64];   // [krow][d]

    const int t  = threadIdx.x;
    const int tx = t & 15;
    const int ty = t >> 4;
    const int qb = blockIdx.x;
    const int h  = blockIdx.y;
    const int b  = blockIdx.z;
    const int q0 = qb * 64;
    const int r0 = ty * 4;
    const int c0 = tx * 4;
    const int lr  = t >> 2;          // 0..63 : tile row
    const int lc4 = (t & 3) * 16;    // 0,16,32,48 : column-quarter base

    const size_t bh = (size_t)(b * Hc + h);
    const float* Qg = g_q + (bh * Sc + q0) * DKc;
    const float* Kg = g_k + bh * Sc * DKc;
    const float* Vg = g_v + bh * Sc * DKc;

    // load Q tile transposed (once) — full coverage: 4 float4 per thread
#pragma unroll
    for (int u = 0; u < 4; u++) {
        const int c = lc4 + u * 4;
        float4 qv = *(const float4*)(Qg + (size_t)lr * DKc + c);
        Qt[c + 0][lr] = qv.x; Qt[c + 1][lr] = qv.y;
        Qt[c + 2][lr] = qv.z; Qt[c + 3][lr] = qv.w;
    }

    const int hg = h >> 1;
    const float* mapB = (hg == 0) ? mIntoken : (hg == 1) ? mInstat
                      : (hg == 2) ? mDataflow : nullptr;
    const float* mapRow[4];
    if (mapB) {
#pragma unroll
        for (int i = 0; i < 4; i++)
            mapRow[i] = mapB + ((size_t)b * Sc + (q0 + r0 + i)) * Sc;
    }

    float m_i[4], l_i[4], acc[4][4] = {};
#pragma unroll
    for (int i = 0; i < 4; i++) { m_i[i] = -INFINITY; l_i[i] = 0.0f; }

    for (int kt = 0; kt < Sc / 64; kt++) {
        const int k0 = kt * 64;
        __syncthreads();  // done with prev tile's P / V (also covers Q store, 1st iter)
#pragma unroll
        for (int u = 0; u < 4; u++) {
            const int c = lc4 + u * 4;
            float4 kv = *(const float4*)(Kg + (size_t)(k0 + lr) * DKc + c);
            KP[c + 0][lr] = kv.x; KP[c + 1][lr] = kv.y;
            KP[c + 2][lr] = kv.z; KP[c + 3][lr] = kv.w;
            *(float4*)&Vs[lr][c] = *(const float4*)(Vg + (size_t)(k0 + lr) * DKc + c);
        }
        __syncthreads();

        // scores: s[i][j] = sum_d Q[q0+r0+i][d] * K[k0+c0+j][d]
        float s[4][4] = {};
#pragma unroll 8
        for (int d = 0; d < 64; d++) {
            float4 a = *(const float4*)&Qt[d][r0];
            float4 k = *(const float4*)&KP[d][c0];
            float aa[4] = {a.x, a.y, a.z, a.w};
            float kk[4] = {k.x, k.y, k.z, k.w};
#pragma unroll
            for (int i = 0; i < 4; i++)
#pragma unroll
                for (int j = 0; j < 4; j++)
                    s[i][j] += aa[i] * kk[j];
        }

        // bias maps (match reference rounding: mul then add, no fma)
        if (hg == 0 || hg == 1) {
#pragma unroll
            for (int i = 0; i < 4; i++) {
                float4 mp = *(const float4*)(mapRow[i] + k0 + c0);
                float mv[4] = {mp.x, mp.y, mp.z, mp.w};
#pragma unroll
                for (int j = 0; j < 4; j++)
                    s[i][j] = __fadd_rn(s[i][j], __fmul_rn(-1.0e9f, mv[j]));
            }
        } else if (hg == 2) {
#pragma unroll
            for (int i = 0; i < 4; i++) {
                float4 mp = *(const float4*)(mapRow[i] + k0 + c0);
                float mv[4] = {mp.x, mp.y, mp.z, mp.w};
#pragma unroll
                for (int j = 0; j < 4; j++)
                    s[i][j] = __fmul_rn(s[i][j],
                               __fadd_rn(1.0f, __fmul_rn(5.0f, mv[j])));
            }
        }

        // key mask (B,1,S) over key dim
        {
            unsigned int mk = *(const unsigned int*)(mask + (size_t)b * Sc + k0 + c0);
            if (mk) {
#pragma unroll
                for (int j = 0; j < 4; j++) {
                    if ((mk >> (8 * j)) & 0xffu) {
#pragma unroll
                        for (int i = 0; i < 4; i++) s[i][j] = -1.0e18f;
                    }
                }
            }
        }

        // online softmax update (rows owned by 16-lane shuffle groups)
#pragma unroll
        for (int i = 0; i < 4; i++) {
            float mx = fmaxf(fmaxf(s[i][0], s[i][1]), fmaxf(s[i][2], s[i][3]));
            mx = fmaxf(mx, __shfl_xor_sync(0xffffffffu, mx, 1));
            mx = fmaxf(mx, __shfl_xor_sync(0xffffffffu, mx, 2));
            mx = fmaxf(mx, __shfl_xor_sync(0xffffffffu, mx, 4));
            mx = fmaxf(mx, __shfl_xor_sync(0xffffffffu, mx, 8));
            const float mn = fmaxf(m_i[i], mx);
            const float sc = __expf(m_i[i] - mn);
            float ps = 0.0f;
#pragma unroll
            for (int j = 0; j < 4; j++) {
                s[i][j] = __expf(s[i][j] - mn);
                ps += s[i][j];
            }
            ps += __shfl_xor_sync(0xffffffffu, ps, 1);
            ps += __shfl_xor_sync(0xffffffffu, ps, 2);
            ps += __shfl_xor_sync(0xffffffffu, ps, 4);
            ps += __shfl_xor_sync(0xffffffffu, ps, 8);
            l_i[i] = l_i[i] * sc + ps;
            m_i[i] = mn;
#pragma unroll
            for (int j = 0; j < 4; j++) acc[i][j] *= sc;
        }

        __syncthreads();  // everyone finished reading KP as K-tile
#pragma unroll
        for (int i = 0; i < 4; i++)
            *(float4*)&KP[r0 + i][c0] = make_float4(s[i][0], s[i][1], s[i][2], s[i][3]);
        __syncthreads();

        // acc += P * V
#pragma unroll 4
        for (int j2 = 0; j2 < 64; j2++) {
            float4 v4 = *(const float4*)&Vs[j2][c0];
            float vv[4] = {v4.x, v4.y, v4.z, v4.w};
#pragma unroll
            for (int i = 0; i < 4; i++) {
                const float p = KP[r0 + i][j2];
#pragma unroll
                for (int j = 0; j < 4; j++) acc[i][j] += p * vv[j];
            }
        }
    }

    // write ctx (B,S,512) at [b][q][h*64 + c]
#pragma unroll
    for (int i = 0; i < 4; i++) {
        const float inv = 1.0f / l_i[i];
        float4 o = make_float4(acc[i][0] * inv, acc[i][1] * inv,
                               acc[i][2] * inv, acc[i][3] * inv);
        *(float4*)(g_ctx + ((size_t)(b * Sc + (q0 + r0 + i))) * Dc + h * DKc + c0) = o;
    }
}

// ---------------------------------------------------------------------------
extern "C" void kernel_launch(void* const* d_in, const int* in_sizes, int n_in,
                              void* d_out, int out_size)
{
    (void)in_sizes; (void)n_in; (void)out_size;
    const float* key_   = (const float*)d_in[0];
    const float* value_ = (const float*)d_in[1];
    const float* query_ = (const float*)d_in[2];
    const float* m_it   = (const float*)d_in[3];
    const float* m_ist  = (const float*)d_in[4];
    const float* m_df   = (const float*)d_in[5];
    const unsigned char* mask = (const unsigned char*)d_in[6];
    const float* Wq = (const float*)d_in[7];
    const float* bq = (const float*)d_in[8];
    const float* Wk = (const float*)d_in[9];
    const float* bk = (const float*)d_in[10];
    const float* Wv = (const float*)d_in[11];
    const float* bv = (const float*)d_in[12];
    const float* Wo = (const float*)d_in[13];
    const float* bo = (const float*)d_in[14];
    float* out = (float*)d_out;

    void *pq, *pk, *pv, *pctx;
    cudaGetSymbolAddress(&pq,   g_q);
    cudaGetSymbolAddress(&pk,   g_k);
    cudaGetSymbolAddress(&pv,   g_v);
    cudaGetSymbolAddress(&pctx, g_ctx);

    dim3 gProj(Dc / 64, (Bc * Sc) / 64);  // (8, 128)
    sgemm_kernel<1><<<gProj, 256>>>(query_, Wq, bq, (float*)pq, 0.125f);
    sgemm_kernel<1><<<gProj, 256>>>(key_,   Wk, bk, (float*)pk, 1.0f);
    sgemm_kernel<1><<<gProj, 256>>>(value_, Wv, bv, (float*)pv, 1.0f);

    attn_kernel<<<dim3(Sc / 64, Hc, Bc), 256>>>(m_it, m_ist, m_df, mask);

    sgemm_kernel<0><<<gProj, 256>>>((const float*)pctx, Wo, bo, out, 1.0f);
}

// round 11
// speedup vs baseline: 1.4067x; 1.4067x over previous
#include <cuda_runtime.h>
#include <cuda_bf16.h>
#include <cstdint>
#include <math.h>

// Problem constants
#define Bc   8
#define Sc   1024
#define Dc   512
#define Hc   8
#define DKc  64

// Scratch (device globals; no allocations allowed)
__device__ float g_q[Bc * Hc * Sc * DKc];    // (B,H,S,64), pre-scaled by 1/8
__device__ float g_k[Bc * Hc * Sc * DKc];
__device__ float g_v[Bc * Hc * Sc * DKc];
__device__ float g_ctx[Bc * Sc * Dc];        // (B,S,512)

// ---------------------------------------------------------------------------
// MMA helpers (legacy warp-level HMMA path; bf16 inputs, fp32 accumulate)
// ---------------------------------------------------------------------------
__device__ __forceinline__ uint32_t smem_u32(const void* p) {
    return (uint32_t)__cvta_generic_to_shared(p);
}
__device__ __forceinline__ void ldsm_x4(uint32_t& r0, uint32_t& r1,
                                        uint32_t& r2, uint32_t& r3, uint32_t addr) {
    asm volatile("ldmatrix.sync.aligned.m8n8.x4.shared.b16 {%0,%1,%2,%3}, [%4];"
                 : "=r"(r0), "=r"(r1), "=r"(r2), "=r"(r3) : "r"(addr));
}
__device__ __forceinline__ void ldsm_x2(uint32_t& r0, uint32_t& r1, uint32_t addr) {
    asm volatile("ldmatrix.sync.aligned.m8n8.x2.shared.b16 {%0,%1}, [%2];"
                 : "=r"(r0), "=r"(r1) : "r"(addr));
}
__device__ __forceinline__ void mma_bf16(float* c, const uint32_t* a, const uint32_t* b) {
    asm volatile("mma.sync.aligned.m16n8k16.row.col.f32.bf16.bf16.f32 "
                 "{%0,%1,%2,%3},{%4,%5,%6,%7},{%8,%9},{%0,%1,%2,%3};"
                 : "+f"(c[0]), "+f"(c[1]), "+f"(c[2]), "+f"(c[3])
                 : "r"(a[0]), "r"(a[1]), "r"(a[2]), "r"(a[3]),
                   "r"(b[0]), "r"(b[1]));
}

// ---------------------------------------------------------------------------
// Split-bf16 tensor-core GEMM: out = X(M x 512) * W(512 x 512)^T + bias.
// x = xh + xl (bf16 split); acc += xh*wh + xh*wl + xl*wh in fp32.
// CTA tile 128x128, BK=32, 256 threads = 8 warps (2m x 4n), 64x32 per warp.
// HEADED=1: out[((b*H+h)*S+s)*64 + d] = (acc+bias)*scale ; else row-major.
// ---------------------------------------------------------------------------
#define BMt  128
#define BNt  128
#define BKt  32
#define PADK 40   // 80B row stride: conflict-free ldmatrix (5i mod 8 perm)

template <int HEADED>
__global__ __launch_bounds__(256)
void mma_gemm(const float* __restrict__ X, const float* __restrict__ W,
              const float* __restrict__ bias, float* __restrict__ out,
              float scale)
{
    __shared__ __align__(16) __nv_bfloat16 Xh[BMt][PADK];
    __shared__ __align__(16) __nv_bfloat16 Xl[BMt][PADK];
    __shared__ __align__(16) __nv_bfloat16 Wh[BNt][PADK];
    __shared__ __align__(16) __nv_bfloat16 Wl[BNt][PADK];

    const int t    = threadIdx.x;
    const int lane = t & 31;
    const int w    = t >> 5;
    const int wm   = w & 1;       // 0..1  -> m offset wm*64
    const int wn   = w >> 1;      // 0..3  -> n offset wn*32
    const int m0   = blockIdx.y * BMt;
    const int n0   = blockIdx.x * BNt;

    const int lrow = t >> 1;           // 0..127
    const int lcb  = (t & 1) * 16;     // 0 or 16

    // ldmatrix per-lane source coordinates
    const int a_row = lane & 15;
    const int a_col = (lane >> 4) * 8;
    const int b_row = lane & 7;
    const int b_col = lane & 8;

    float acc[4][4][4];
#pragma unroll
    for (int i = 0; i < 4; i++)
#pragma unroll
        for (int j = 0; j < 4; j++)
#pragma unroll
            for (int e = 0; e < 4; e++) acc[i][j][e] = 0.0f;

    const float* Xp = X + (size_t)(m0 + lrow) * 512 + lcb;
    const float* Wp = W + (size_t)(n0 + lrow) * 512 + lcb;

    for (int k0 = 0; k0 < 512; k0 += BKt) {
        __syncthreads();
#pragma unroll
        for (int u = 0; u < 4; u++) {
            const int c = lcb + u * 4;
            float4 xv = *(const float4*)(Xp + k0 + u * 4);
            float4 wv = *(const float4*)(Wp + k0 + u * 4);
            float xs[4] = {xv.x, xv.y, xv.z, xv.w};
            float ws[4] = {wv.x, wv.y, wv.z, wv.w};
#pragma unroll
            for (int e = 0; e < 4; e++) {
                __nv_bfloat16 hx = __float2bfloat16(xs[e]);
                Xh[lrow][c + e] = hx;
                Xl[lrow][c + e] = __float2bfloat16(xs[e] - __bfloat162float(hx));
                __nv_bfloat16 hw = __float2bfloat16(ws[e]);
                Wh[lrow][c + e] = hw;
                Wl[lrow][c + e] = __float2bfloat16(ws[e] - __bfloat162float(hw));
            }
        }
        __syncthreads();

#pragma unroll
        for (int k16 = 0; k16 < BKt; k16 += 16) {
            uint32_t ah[4][4], al[4][4], bh[4][2], bl[4][2];
#pragma unroll
            for (int mt = 0; mt < 4; mt++) {
                const int r = wm * 64 + mt * 16 + a_row;
                ldsm_x4(ah[mt][0], ah[mt][1], ah[mt][2], ah[mt][3],
                        smem_u32(&Xh[r][k16 + a_col]));
                ldsm_x4(al[mt][0], al[mt][1], al[mt][2], al[mt][3],
                        smem_u32(&Xl[r][k16 + a_col]));
            }
#pragma unroll
            for (int nt = 0; nt < 4; nt++) {
                const int r = wn * 32 + nt * 8 + b_row;
                ldsm_x2(bh[nt][0], bh[nt][1], smem_u32(&Wh[r][k16 + b_col]));
                ldsm_x2(bl[nt][0], bl[nt][1], smem_u32(&Wl[r][k16 + b_col]));
            }
#pragma unroll
            for (int mt = 0; mt < 4; mt++)
#pragma unroll
                for (int nt = 0; nt < 4; nt++) {
                    mma_bf16(acc[mt][nt], ah[mt], bh[nt]);
                    mma_bf16(acc[mt][nt], ah[mt], bl[nt]);
                    mma_bf16(acc[mt][nt], al[mt], bh[nt]);
                }
        }
    }

    // Epilogue: c0,c1 -> (row, col..col+1); c2,c3 -> row+8.
    const int er = lane >> 2;
    const int ec = (lane & 3) * 2;
#pragma unroll
    for (int mt = 0; mt < 4; mt++) {
#pragma unroll
        for (int nt = 0; nt < 4; nt++) {
            const int o = n0 + wn * 32 + nt * 8 + ec;
            const float b0 = bias[o], b1 = bias[o + 1];
#pragma unroll
            for (int half = 0; half < 2; half++) {
                const int m = m0 + wm * 64 + mt * 16 + er + half * 8;
                float2 r;
                r.x = (acc[mt][nt][half * 2 + 0] + b0) * scale;
                r.y = (acc[mt][nt][half * 2 + 1] + b1) * scale;
                if (HEADED) {
                    const int h = o >> 6, d = o & 63;
                    const int b = m >> 10, s = m & 1023;
                    *(float2*)(out + (((size_t)(b * Hc + h) * Sc + s) * DKc + d)) = r;
                } else {
                    *(float2*)(out + (size_t)m * 512 + o) = r;
                }
            }
        }
    }
}

// ---------------------------------------------------------------------------
// Flash-style attention. One CTA = (b, h, 64 q-rows). 256 threads. (unchanged)
// ---------------------------------------------------------------------------
__global__ __launch_bounds__(256)
void attn_kernel(const float* __restrict__ mIntoken,
                 const float* __restrict__ mInstat,
                 const float* __restrict__ mDataflow,
                 const unsigned char* __restrict__ mask)
{
    __shared__ __align__(16) float Qt[64][64];   // [d][qrow]
    __shared__ __align__(16) float KP[64][64];   // Kt: [d][krow]; then P: [qrow][kcol]
    __shared__ __align__(16) float Vs[64][64];   // [krow][d]

    const int t  = threadIdx.x;
    const int tx = t & 15;
    const int ty = t >> 4;
    const int qb = blockIdx.x;
    const int h  = blockIdx.y;
    const int b  = blockIdx.z;
    const int q0 = qb * 64;
    const int r0 = ty * 4;
    const int c0 = tx * 4;
    const int lr  = t >> 2;          // 0..63 : tile row
    const int lc4 = (t & 3) * 16;    // 0,16,32,48 : column-quarter base

    const size_t bh = (size_t)(b * Hc + h);
    const float* Qg = g_q + (bh * Sc + q0) * DKc;
    const float* Kg = g_k + bh * Sc * DKc;
    const float* Vg = g_v + bh * Sc * DKc;

    // load Q tile transposed (once) — full coverage: 4 float4 per thread
#pragma unroll
    for (int u = 0; u < 4; u++) {
        const int c = lc4 + u * 4;
        float4 qv = *(const float4*)(Qg + (size_t)lr * DKc + c);
        Qt[c + 0][lr] = qv.x; Qt[c + 1][lr] = qv.y;
        Qt[c + 2][lr] = qv.z; Qt[c + 3][lr] = qv.w;
    }

    const int hg = h >> 1;
    const float* mapB = (hg == 0) ? mIntoken : (hg == 1) ? mInstat
                      : (hg == 2) ? mDataflow : nullptr;
    const float* mapRow[4];
    if (mapB) {
#pragma unroll
        for (int i = 0; i < 4; i++)
            mapRow[i] = mapB + ((size_t)b * Sc + (q0 + r0 + i)) * Sc;
    }

    float m_i[4], l_i[4], acc[4][4] = {};
#pragma unroll
    for (int i = 0; i < 4; i++) { m_i[i] = -INFINITY; l_i[i] = 0.0f; }

    for (int kt = 0; kt < Sc / 64; kt++) {
        const int k0 = kt * 64;
        __syncthreads();  // done with prev tile's P / V (also covers Q store, 1st iter)
#pragma unroll
        for (int u = 0; u < 4; u++) {
            const int c = lc4 + u * 4;
            float4 kv = *(const float4*)(Kg + (size_t)(k0 + lr) * DKc + c);
            KP[c + 0][lr] = kv.x; KP[c + 1][lr] = kv.y;
            KP[c + 2][lr] = kv.z; KP[c + 3][lr] = kv.w;
            *(float4*)&Vs[lr][c] = *(const float4*)(Vg + (size_t)(k0 + lr) * DKc + c);
        }
        __syncthreads();

        // scores: s[i][j] = sum_d Q[q0+r0+i][d] * K[k0+c0+j][d]
        float s[4][4] = {};
#pragma unroll 8
        for (int d = 0; d < 64; d++) {
            float4 a = *(const float4*)&Qt[d][r0];
            float4 k = *(const float4*)&KP[d][c0];
            float aa[4] = {a.x, a.y, a.z, a.w};
            float kk[4] = {k.x, k.y, k.z, k.w};
#pragma unroll
            for (int i = 0; i < 4; i++)
#pragma unroll
                for (int j = 0; j < 4; j++)
                    s[i][j] += aa[i] * kk[j];
        }

        // bias maps (match reference rounding: mul then add, no fma)
        if (hg == 0 || hg == 1) {
#pragma unroll
            for (int i = 0; i < 4; i++) {
                float4 mp = *(const float4*)(mapRow[i] + k0 + c0);
                float mv[4] = {mp.x, mp.y, mp.z, mp.w};
#pragma unroll
                for (int j = 0; j < 4; j++)
                    s[i][j] = __fadd_rn(s[i][j], __fmul_rn(-1.0e9f, mv[j]));
            }
        } else if (hg == 2) {
#pragma unroll
            for (int i = 0; i < 4; i++) {
                float4 mp = *(const float4*)(mapRow[i] + k0 + c0);
                float mv[4] = {mp.x, mp.y, mp.z, mp.w};
#pragma unroll
                for (int j = 0; j < 4; j++)
                    s[i][j] = __fmul_rn(s[i][j],
                               __fadd_rn(1.0f, __fmul_rn(5.0f, mv[j])));
            }
        }

        // key mask (B,1,S) over key dim
        {
            unsigned int mk = *(const unsigned int*)(mask + (size_t)b * Sc + k0 + c0);
            if (mk) {
#pragma unroll
                for (int j = 0; j < 4; j++) {
                    if ((mk >> (8 * j)) & 0xffu) {
#pragma unroll
                        for (int i = 0; i < 4; i++) s[i][j] = -1.0e18f;
                    }
                }
            }
        }

        // online softmax update (rows owned by 16-lane shuffle groups)
#pragma unroll
        for (int i = 0; i < 4; i++) {
            float mx = fmaxf(fmaxf(s[i][0], s[i][1]), fmaxf(s[i][2], s[i][3]));
            mx = fmaxf(mx, __shfl_xor_sync(0xffffffffu, mx, 1));
            mx = fmaxf(mx, __shfl_xor_sync(0xffffffffu, mx, 2));
            mx = fmaxf(mx, __shfl_xor_sync(0xffffffffu, mx, 4));
            mx = fmaxf(mx, __shfl_xor_sync(0xffffffffu, mx, 8));
            const float mn = fmaxf(m_i[i], mx);
            const float sc = __expf(m_i[i] - mn);
            float ps = 0.0f;
#pragma unroll
            for (int j = 0; j < 4; j++) {
                s[i][j] = __expf(s[i][j] - mn);
                ps += s[i][j];
            }
            ps += __shfl_xor_sync(0xffffffffu, ps, 1);
            ps += __shfl_xor_sync(0xffffffffu, ps, 2);
            ps += __shfl_xor_sync(0xffffffffu, ps, 4);
            ps += __shfl_xor_sync(0xffffffffu, ps, 8);
            l_i[i] = l_i[i] * sc + ps;
            m_i[i] = mn;
#pragma unroll
            for (int j = 0; j < 4; j++) acc[i][j] *= sc;
        }

        __syncthreads();  // everyone finished reading KP as K-tile
#pragma unroll
        for (int i = 0; i < 4; i++)
            *(float4*)&KP[r0 + i][c0] = make_float4(s[i][0], s[i][1], s[i][2], s[i][3]);
        __syncthreads();

        // acc += P * V
#pragma unroll 4
        for (int j2 = 0; j2 < 64; j2++) {
            float4 v4 = *(const float4*)&Vs[j2][c0];
            float vv[4] = {v4.x, v4.y, v4.z, v4.w};
#pragma unroll
            for (int i = 0; i < 4; i++) {
                const float p = KP[r0 + i][j2];
#pragma unroll
                for (int j = 0; j < 4; j++) acc[i][j] += p * vv[j];
            }
        }
    }

    // write ctx (B,S,512) at [b][q][h*64 + c]
#pragma unroll
    for (int i = 0; i < 4; i++) {
        const float inv = 1.0f / l_i[i];
        float4 o = make_float4(acc[i][0] * inv, acc[i][1] * inv,
                               acc[i][2] * inv, acc[i][3] * inv);
        *(float4*)(g_ctx + ((size_t)(b * Sc + (q0 + r0 + i))) * Dc + h * DKc + c0) = o;
    }
}

// ---------------------------------------------------------------------------
extern "C" void kernel_launch(void* const* d_in, const int* in_sizes, int n_in,
                              void* d_out, int out_size)
{
    (void)in_sizes; (void)n_in; (void)out_size;
    const float* key_   = (const float*)d_in[0];
    const float* value_ = (const float*)d_in[1];
    const float* query_ = (const float*)d_in[2];
    const float* m_it   = (const float*)d_in[3];
    const float* m_ist  = (const float*)d_in[4];
    const float* m_df   = (const float*)d_in[5];
    const unsigned char* mask = (const unsigned char*)d_in[6];
    const float* Wq = (const float*)d_in[7];
    const float* bq = (const float*)d_in[8];
    const float* Wk = (const float*)d_in[9];
    const float* bk = (const float*)d_in[10];
    const float* Wv = (const float*)d_in[11];
    const float* bv = (const float*)d_in[12];
    const float* Wo = (const float*)d_in[13];
    const float* bo = (const float*)d_in[14];
    float* out = (float*)d_out;

    void *pq, *pk, *pv, *pctx;
    cudaGetSymbolAddress(&pq,   g_q);
    cudaGetSymbolAddress(&pk,   g_k);
    cudaGetSymbolAddress(&pv,   g_v);
    cudaGetSymbolAddress(&pctx, g_ctx);

    dim3 gProj(Dc / BNt, (Bc * Sc) / BMt);  // (4, 64)
    mma_gemm<1><<<gProj, 256>>>(query_, Wq, bq, (float*)pq, 0.125f);
    mma_gemm<1><<<gProj, 256>>>(key_,   Wk, bk, (float*)pk, 1.0f);
    mma_gemm<1><<<gProj, 256>>>(value_, Wv, bv, (float*)pv, 1.0f);

    attn_kernel<<<dim3(Sc / 64, Hc, Bc), 256>>>(m_it, m_ist, m_df, mask);

    mma_gemm<0><<<gProj, 256>>>((const float*)pctx, Wo, bo, out, 1.0f);
}

// round 13
// speedup vs baseline: 1.9090x; 1.3570x over previous
#include <cuda_runtime.h>
#include <cuda_bf16.h>
#include <cstdint>
#include <math.h>

// Problem constants
#define Bc   8
#define Sc   1024
#define Dc   512
#define Hc   8
#define DKc  64

// Scratch (device globals; no allocations allowed)
__device__ float g_q[Bc * Hc * Sc * DKc];    // (B,H,S,64), pre-scaled by 1/8
__device__ float g_k[Bc * Hc * Sc * DKc];
__device__ float g_v[Bc * Hc * Sc * DKc];
__device__ float g_ctx[Bc * Sc * Dc];        // (B,S,512)

// ---------------------------------------------------------------------------
// MMA helpers (warp-level HMMA; bf16 inputs, fp32 accumulate)
// ---------------------------------------------------------------------------
__device__ __forceinline__ uint32_t smem_u32(const void* p) {
    return (uint32_t)__cvta_generic_to_shared(p);
}
__device__ __forceinline__ void ldsm_x4(uint32_t& r0, uint32_t& r1,
                                        uint32_t& r2, uint32_t& r3, uint32_t addr) {
    asm volatile("ldmatrix.sync.aligned.m8n8.x4.shared.b16 {%0,%1,%2,%3}, [%4];"
                 : "=r"(r0), "=r"(r1), "=r"(r2), "=r"(r3) : "r"(addr));
}
__device__ __forceinline__ void ldsm_x2(uint32_t& r0, uint32_t& r1, uint32_t addr) {
    asm volatile("ldmatrix.sync.aligned.m8n8.x2.shared.b16 {%0,%1}, [%2];"
                 : "=r"(r0), "=r"(r1) : "r"(addr));
}
__device__ __forceinline__ void mma_bf16(float* c, const uint32_t* a, const uint32_t* b) {
    asm volatile("mma.sync.aligned.m16n8k16.row.col.f32.bf16.bf16.f32 "
                 "{%0,%1,%2,%3},{%4,%5,%6,%7},{%8,%9},{%0,%1,%2,%3};"
                 : "+f"(c[0]), "+f"(c[1]), "+f"(c[2]), "+f"(c[3])
                 : "r"(a[0]), "r"(a[1]), "r"(a[2]), "r"(a[3]),
                   "r"(b[0]), "r"(b[1]));
}
// split float pair (x=low k, y=high k) into packed bf16x2 hi & lo parts
__device__ __forceinline__ void split2(float x, float y, uint32_t& hi, uint32_t& lo) {
    __nv_bfloat16 hx = __float2bfloat16(x), hy = __float2bfloat16(y);
    __nv_bfloat16 lx = __float2bfloat16(x - __bfloat162float(hx));
    __nv_bfloat16 ly = __float2bfloat16(y - __bfloat162float(hy));
    hi = (uint32_t)__bfloat16_as_ushort(hx) | ((uint32_t)__bfloat16_as_ushort(hy) << 16);
    lo = (uint32_t)__bfloat16_as_ushort(lx) | ((uint32_t)__bfloat16_as_ushort(ly) << 16);
}

// ---------------------------------------------------------------------------
// Split-bf16 tensor-core GEMM (unchanged, known-good): out = X*W^T + bias
// ---------------------------------------------------------------------------
#define BMt  128
#define BNt  128
#define BKt  32
#define PADK 40

template <int HEADED>
__global__ __launch_bounds__(256)
void mma_gemm(const float* __restrict__ X, const float* __restrict__ W,
              const float* __restrict__ bias, float* __restrict__ out,
              float scale)
{
    __shared__ __align__(16) __nv_bfloat16 Xh[BMt][PADK];
    __shared__ __align__(16) __nv_bfloat16 Xl[BMt][PADK];
    __shared__ __align__(16) __nv_bfloat16 Wh[BNt][PADK];
    __shared__ __align__(16) __nv_bfloat16 Wl[BNt][PADK];

    const int t    = threadIdx.x;
    const int lane = t & 31;
    const int w    = t >> 5;
    const int wm   = w & 1;
    const int wn   = w >> 1;
    const int m0   = blockIdx.y * BMt;
    const int n0   = blockIdx.x * BNt;

    const int lrow = t >> 1;
    const int lcb  = (t & 1) * 16;

    const int a_row = lane & 15;
    const int a_col = (lane >> 4) * 8;
    const int b_row = lane & 7;
    const int b_col = lane & 8;

    float acc[4][4][4];
#pragma unroll
    for (int i = 0; i < 4; i++)
#pragma unroll
        for (int j = 0; j < 4; j++)
#pragma unroll
            for (int e = 0; e < 4; e++) acc[i][j][e] = 0.0f;

    const float* Xp = X + (size_t)(m0 + lrow) * 512 + lcb;
    const float* Wp = W + (size_t)(n0 + lrow) * 512 + lcb;

    for (int k0 = 0; k0 < 512; k0 += BKt) {
        __syncthreads();
#pragma unroll
        for (int u = 0; u < 4; u++) {
            const int c = lcb + u * 4;
            float4 xv = *(const float4*)(Xp + k0 + u * 4);
            float4 wv = *(const float4*)(Wp + k0 + u * 4);
            uint32_t hi, lo;
            split2(xv.x, xv.y, hi, lo);
            *(uint32_t*)&Xh[lrow][c] = hi;     *(uint32_t*)&Xl[lrow][c] = lo;
            split2(xv.z, xv.w, hi, lo);
            *(uint32_t*)&Xh[lrow][c + 2] = hi; *(uint32_t*)&Xl[lrow][c + 2] = lo;
            split2(wv.x, wv.y, hi, lo);
            *(uint32_t*)&Wh[lrow][c] = hi;     *(uint32_t*)&Wl[lrow][c] = lo;
            split2(wv.z, wv.w, hi, lo);
            *(uint32_t*)&Wh[lrow][c + 2] = hi; *(uint32_t*)&Wl[lrow][c + 2] = lo;
        }
        __syncthreads();

#pragma unroll
        for (int k16 = 0; k16 < BKt; k16 += 16) {
            uint32_t ah[4][4], al[4][4], bh[4][2], bl[4][2];
#pragma unroll
            for (int mt = 0; mt < 4; mt++) {
                const int r = wm * 64 + mt * 16 + a_row;
                ldsm_x4(ah[mt][0], ah[mt][1], ah[mt][2], ah[mt][3],
                        smem_u32(&Xh[r][k16 + a_col]));
                ldsm_x4(al[mt][0], al[mt][1], al[mt][2], al[mt][3],
                        smem_u32(&Xl[r][k16 + a_col]));
            }
#pragma unroll
            for (int nt = 0; nt < 4; nt++) {
                const int r = wn * 32 + nt * 8 + b_row;
                ldsm_x2(bh[nt][0], bh[nt][1], smem_u32(&Wh[r][k16 + b_col]));
                ldsm_x2(bl[nt][0], bl[nt][1], smem_u32(&Wl[r][k16 + b_col]));
            }
#pragma unroll
            for (int mt = 0; mt < 4; mt++)
#pragma unroll
                for (int nt = 0; nt < 4; nt++) {
                    mma_bf16(acc[mt][nt], ah[mt], bh[nt]);
                    mma_bf16(acc[mt][nt], ah[mt], bl[nt]);
                    mma_bf16(acc[mt][nt], al[mt], bh[nt]);
                }
        }
    }

    const int er = lane >> 2;
    const int ec = (lane & 3) * 2;
#pragma unroll
    for (int mt = 0; mt < 4; mt++) {
#pragma unroll
        for (int nt = 0; nt < 4; nt++) {
            const int o = n0 + wn * 32 + nt * 8 + ec;
            const float b0 = bias[o], b1 = bias[o + 1];
#pragma unroll
            for (int half = 0; half < 2; half++) {
                const int m = m0 + wm * 64 + mt * 16 + er + half * 8;
                float2 r;
                r.x = (acc[mt][nt][half * 2 + 0] + b0) * scale;
                r.y = (acc[mt][nt][half * 2 + 1] + b1) * scale;
                if (HEADED) {
                    const int h = o >> 6, d = o & 63;
                    const int b = m >> 10, s = m & 1023;
                    *(float2*)(out + (((size_t)(b * Hc + h) * Sc + s) * DKc + d)) = r;
                } else {
                    *(float2*)(out + (size_t)m * 512 + o) = r;
                }
            }
        }
    }
}

// ---------------------------------------------------------------------------
// Tensor-core flash attention. CTA = (b, h, 64 q-rows); 256 thr = 8 warps
// (wm=w&3 -> 16 q-rows, wn=w>>2 -> half of k/d cols). k-tile = 32 keys.
// QK^T and P*V both split-bf16 (3 MMAs), fp32 accum. Softmax in fragment
// layout with [2][64] smem cross-warp reductions; m/l state in smem.
// Extra barrier between all-lane m/l reads and owner m/l writes (race fix).
// ---------------------------------------------------------------------------
#define KT  32

__global__ __launch_bounds__(256)
void attn_mma(const float* __restrict__ mIntoken,
              const float* __restrict__ mInstat,
              const float* __restrict__ mDataflow,
              const unsigned char* __restrict__ mask)
{
    __shared__ __align__(16) __nv_bfloat16 Kh[32][72], Kl[32][72];   // key x d
    __shared__ __align__(16) __nv_bfloat16 Vth[64][40], Vtl[64][40]; // d x key
    __shared__ __align__(16) __nv_bfloat16 Ph[64][40], Pl[64][40];   // q x key
    __shared__ float redmax[2][64], redsum[2][64], marr[64], larr[64];

    const int t    = threadIdx.x;
    const int lane = t & 31;
    const int w    = t >> 5;
    const int wm   = w & 3;    // q band: wm*16
    const int wn   = w >> 2;   // 0..1
    const int q0   = blockIdx.x * 64;
    const int h    = blockIdx.y;
    const int b    = blockIdx.z;

    const int er = lane >> 2;          // fragment row within 8
    const int ec = (lane & 3) * 2;     // fragment col pair
    const int a_row = lane & 15;
    const int a_col = (lane >> 4) * 8;
    const int b_row = lane & 7;
    const int b_col = lane & 8;

    const size_t bh = (size_t)(b * Hc + h);
    const float* Qg = g_q + (bh * Sc + q0) * DKc;
    const float* Kg = g_k + bh * Sc * DKc;
    const float* Vg = g_v + bh * Sc * DKc;

    const int rlo = wm * 16 + er;      // CTA-local q rows this lane owns
    const int rhi = rlo + 8;

    // ---- Q fragments in registers (hi/lo), rows rlo/rhi, all 64 d ----
    uint32_t qh[4][4], ql[4][4];
#pragma unroll
    for (int kk = 0; kk < 4; kk++) {
        const int c = kk * 16 + ec;
        float2 f0 = *(const float2*)(Qg + (size_t)rlo * DKc + c);
        float2 f1 = *(const float2*)(Qg + (size_t)rhi * DKc + c);
        float2 f2 = *(const float2*)(Qg + (size_t)rlo * DKc + c + 8);
        float2 f3 = *(const float2*)(Qg + (size_t)rhi * DKc + c + 8);
        split2(f0.x, f0.y, qh[kk][0], ql[kk][0]);
        split2(f1.x, f1.y, qh[kk][1], ql[kk][1]);
        split2(f2.x, f2.y, qh[kk][2], ql[kk][2]);
        split2(f3.x, f3.y, qh[kk][3], ql[kk][3]);
    }

    if (t < 64) { marr[t] = -INFINITY; larr[t] = 0.0f; }

    const int hg = h >> 1;
    const float* mapB = (hg == 0) ? mIntoken : (hg == 1) ? mInstat
                      : (hg == 2) ? mDataflow : nullptr;
    const float* mr_lo = mapB ? mapB + ((size_t)b * Sc + q0 + rlo) * Sc : nullptr;
    const float* mr_hi = mapB ? mapB + ((size_t)b * Sc + q0 + rhi) * Sc : nullptr;

    float acc[4][4];   // PV accum: 4 d-ntiles x 4
#pragma unroll
    for (int i = 0; i < 4; i++)
#pragma unroll
        for (int j = 0; j < 4; j++) acc[i][j] = 0.0f;

    // K-tile staging coords
    const int k_row = t >> 3, k_cb = (t & 7) * 8;     // K: 32 rows x 64 cols
    const int v_key = t & 31, v_cb = (t >> 5) * 8;    // V: 32 keys, transpose

    for (int kt = 0; kt < Sc / KT; kt++) {
        const int k0 = kt * KT;
        __syncthreads();   // prev tile's MMAs done; safe to overwrite smem (also covers marr init)

        // stage K (hi/lo) [key][d]
        {
            const float* kp = Kg + (size_t)(k0 + k_row) * DKc + k_cb;
            float4 v1 = *(const float4*)kp;
            float4 v2 = *(const float4*)(kp + 4);
            uint32_t hi, lo;
            split2(v1.x, v1.y, hi, lo);
            *(uint32_t*)&Kh[k_row][k_cb + 0] = hi; *(uint32_t*)&Kl[k_row][k_cb + 0] = lo;
            split2(v1.z, v1.w, hi, lo);
            *(uint32_t*)&Kh[k_row][k_cb + 2] = hi; *(uint32_t*)&Kl[k_row][k_cb + 2] = lo;
            split2(v2.x, v2.y, hi, lo);
            *(uint32_t*)&Kh[k_row][k_cb + 4] = hi; *(uint32_t*)&Kl[k_row][k_cb + 4] = lo;
            split2(v2.z, v2.w, hi, lo);
            *(uint32_t*)&Kh[k_row][k_cb + 6] = hi; *(uint32_t*)&Kl[k_row][k_cb + 6] = lo;
        }
        // stage V transposed (hi/lo) [d][key]
        {
            const float* vp = Vg + (size_t)(k0 + v_key) * DKc + v_cb;
            float4 v1 = *(const float4*)vp;
            float4 v2 = *(const float4*)(vp + 4);
            float f[8] = {v1.x, v1.y, v1.z, v1.w, v2.x, v2.y, v2.z, v2.w};
#pragma unroll
            for (int e = 0; e < 8; e++) {
                __nv_bfloat16 hx = __float2bfloat16(f[e]);
                Vth[v_cb + e][v_key] = hx;
                Vtl[v_cb + e][v_key] = __float2bfloat16(f[e] - __bfloat162float(hx));
            }
        }
        __syncthreads();

        // ---- S = Q K^T (fragments) ----
        float s[2][4] = {};
#pragma unroll
        for (int kk = 0; kk < 4; kk++) {
#pragma unroll
            for (int nt = 0; nt < 2; nt++) {
                uint32_t bhv[2], blv[2];
                const int r = wn * 16 + nt * 8 + b_row;
                ldsm_x2(bhv[0], bhv[1], smem_u32(&Kh[r][kk * 16 + b_col]));
                ldsm_x2(blv[0], blv[1], smem_u32(&Kl[r][kk * 16 + b_col]));
                mma_bf16(s[nt], qh[kk], bhv);
                mma_bf16(s[nt], qh[kk], blv);
                mma_bf16(s[nt], ql[kk], bhv);
            }
        }

        // ---- bias maps + mask in fragment layout ----
#pragma unroll
        for (int nt = 0; nt < 2; nt++) {
            const int cg = k0 + wn * 16 + nt * 8 + ec;  // global key col
            if (hg == 0 || hg == 1) {
                float2 mlo = *(const float2*)(mr_lo + cg);
                float2 mhi = *(const float2*)(mr_hi + cg);
                s[nt][0] = __fadd_rn(s[nt][0], __fmul_rn(-1.0e9f, mlo.x));
                s[nt][1] = __fadd_rn(s[nt][1], __fmul_rn(-1.0e9f, mlo.y));
                s[nt][2] = __fadd_rn(s[nt][2], __fmul_rn(-1.0e9f, mhi.x));
                s[nt][3] = __fadd_rn(s[nt][3], __fmul_rn(-1.0e9f, mhi.y));
            } else if (hg == 2) {
                float2 mlo = *(const float2*)(mr_lo + cg);
                float2 mhi = *(const float2*)(mr_hi + cg);
                s[nt][0] = __fmul_rn(s[nt][0], __fadd_rn(1.0f, __fmul_rn(5.0f, mlo.x)));
                s[nt][1] = __fmul_rn(s[nt][1], __fadd_rn(1.0f, __fmul_rn(5.0f, mlo.y)));
                s[nt][2] = __fmul_rn(s[nt][2], __fadd_rn(1.0f, __fmul_rn(5.0f, mhi.x)));
                s[nt][3] = __fmul_rn(s[nt][3], __fadd_rn(1.0f, __fmul_rn(5.0f, mhi.y)));
            }
            const unsigned char* mp = mask + (size_t)b * Sc + cg;
            if (mp[0]) { s[nt][0] = -1.0e18f; s[nt][2] = -1.0e18f; }
            if (mp[1]) { s[nt][1] = -1.0e18f; s[nt][3] = -1.0e18f; }
        }

        // ---- row max (warp part) ----
        float mx_lo = fmaxf(fmaxf(s[0][0], s[0][1]), fmaxf(s[1][0], s[1][1]));
        float mx_hi = fmaxf(fmaxf(s[0][2], s[0][3]), fmaxf(s[1][2], s[1][3]));
        mx_lo = fmaxf(mx_lo, __shfl_xor_sync(0xffffffffu, mx_lo, 1));
        mx_lo = fmaxf(mx_lo, __shfl_xor_sync(0xffffffffu, mx_lo, 2));
        mx_hi = fmaxf(mx_hi, __shfl_xor_sync(0xffffffffu, mx_hi, 1));
        mx_hi = fmaxf(mx_hi, __shfl_xor_sync(0xffffffffu, mx_hi, 2));
        if ((lane & 3) == 0) {
            redmax[wn][rlo] = mx_lo;
            redmax[wn][rhi] = mx_hi;
        }
        __syncthreads();

        // ---- online softmax: exp + partial sums + P store ----
        const float mo_lo = marr[rlo], mo_hi = marr[rhi];
        const float tm_lo = fmaxf(redmax[0][rlo], redmax[1][rlo]);
        const float tm_hi = fmaxf(redmax[0][rhi], redmax[1][rhi]);
        const float mn_lo = fmaxf(mo_lo, tm_lo);
        const float mn_hi = fmaxf(mo_hi, tm_hi);
        const float sc_lo = __expf(mo_lo - mn_lo);
        const float sc_hi = __expf(mo_hi - mn_hi);

        float ps_lo = 0.0f, ps_hi = 0.0f;
#pragma unroll
        for (int nt = 0; nt < 2; nt++) {
            float p0 = __expf(s[nt][0] - mn_lo);
            float p1 = __expf(s[nt][1] - mn_lo);
            float p2 = __expf(s[nt][2] - mn_hi);
            float p3 = __expf(s[nt][3] - mn_hi);
            ps_lo += p0 + p1;
            ps_hi += p2 + p3;
            const int cb = wn * 16 + nt * 8 + ec;
            uint32_t hi, lo;
            split2(p0, p1, hi, lo);
            *(uint32_t*)&Ph[rlo][cb] = hi; *(uint32_t*)&Pl[rlo][cb] = lo;
            split2(p2, p3, hi, lo);
            *(uint32_t*)&Ph[rhi][cb] = hi; *(uint32_t*)&Pl[rhi][cb] = lo;
        }
        ps_lo += __shfl_xor_sync(0xffffffffu, ps_lo, 1);
        ps_lo += __shfl_xor_sync(0xffffffffu, ps_lo, 2);
        ps_hi += __shfl_xor_sync(0xffffffffu, ps_hi, 1);
        ps_hi += __shfl_xor_sync(0xffffffffu, ps_hi, 2);
        if ((lane & 3) == 0) {
            redsum[wn][rlo] = ps_lo;
            redsum[wn][rhi] = ps_hi;
        }
        __syncthreads();   // redsum complete; all lanes already hold mo/mn/sc in regs

        // l/m update (one owner per row), acc rescale (everyone)
        if (wn == 0 && (lane & 3) == 0) {
            larr[rlo] = larr[rlo] * sc_lo + redsum[0][rlo] + redsum[1][rlo];
            larr[rhi] = larr[rhi] * sc_hi + redsum[0][rhi] + redsum[1][rhi];
            marr[rlo] = mn_lo;
            marr[rhi] = mn_hi;
        }
#pragma unroll
        for (int nt = 0; nt < 4; nt++) {
            acc[nt][0] *= sc_lo; acc[nt][1] *= sc_lo;
            acc[nt][2] *= sc_hi; acc[nt][3] *= sc_hi;
        }

        // ---- acc += P V ----
#pragma unroll
        for (int k16 = 0; k16 < KT; k16 += 16) {
            uint32_t pah[4], pal[4];
            ldsm_x4(pah[0], pah[1], pah[2], pah[3],
                    smem_u32(&Ph[wm * 16 + a_row][k16 + a_col]));
            ldsm_x4(pal[0], pal[1], pal[2], pal[3],
                    smem_u32(&Pl[wm * 16 + a_row][k16 + a_col]));
#pragma unroll
            for (int nt = 0; nt < 4; nt++) {
                uint32_t bhv[2], blv[2];
                const int r = wn * 32 + nt * 8 + b_row;
                ldsm_x2(bhv[0], bhv[1], smem_u32(&Vth[r][k16 + b_col]));
                ldsm_x2(blv[0], blv[1], smem_u32(&Vtl[r][k16 + b_col]));
                mma_bf16(acc[nt], pah, bhv);
                mma_bf16(acc[nt], pah, blv);
                mma_bf16(acc[nt], pal, bhv);
            }
        }
    }

    __syncthreads();   // larr final writes visible
    const float linv_lo = 1.0f / larr[rlo];
    const float linv_hi = 1.0f / larr[rhi];

    // write ctx (B,S,512): row q0+r, col h*64 + (wn*32 + nt*8 + ec)
#pragma unroll
    for (int nt = 0; nt < 4; nt++) {
        const int d = wn * 32 + nt * 8 + ec;
        float2 o0 = make_float2(acc[nt][0] * linv_lo, acc[nt][1] * linv_lo);
        float2 o1 = make_float2(acc[nt][2] * linv_hi, acc[nt][3] * linv_hi);
        *(float2*)(g_ctx + ((size_t)(b * Sc + q0 + rlo)) * Dc + h * DKc + d) = o0;
        *(float2*)(g_ctx + ((size_t)(b * Sc + q0 + rhi)) * Dc + h * DKc + d) = o1;
    }
}

// ---------------------------------------------------------------------------
extern "C" void kernel_launch(void* const* d_in, const int* in_sizes, int n_in,
                              void* d_out, int out_size)
{
    (void)in_sizes; (void)n_in; (void)out_size;
    const float* key_   = (const float*)d_in[0];
    const float* value_ = (const float*)d_in[1];
    const float* query_ = (const float*)d_in[2];
    const float* m_it   = (const float*)d_in[3];
    const float* m_ist  = (const float*)d_in[4];
    const float* m_df   = (const float*)d_in[5];
    const unsigned char* mask = (const unsigned char*)d_in[6];
    const float* Wq = (const float*)d_in[7];
    const float* bq = (const float*)d_in[8];
    const float* Wk = (const float*)d_in[9];
    const float* bk = (const float*)d_in[10];
    const float* Wv = (const float*)d_in[11];
    const float* bv = (const float*)d_in[12];
    const float* Wo = (const float*)d_in[13];
    const float* bo = (const float*)d_in[14];
    float* out = (float*)d_out;

    void *pq, *pk, *pv, *pctx;
    cudaGetSymbolAddress(&pq,   g_q);
    cudaGetSymbolAddress(&pk,   g_k);
    cudaGetSymbolAddress(&pv,   g_v);
    cudaGetSymbolAddress(&pctx, g_ctx);

    dim3 gProj(Dc / BNt, (Bc * Sc) / BMt);  // (4, 64)
    mma_gemm<1><<<gProj, 256>>>(query_, Wq, bq, (float*)pq, 0.125f);
    mma_gemm<1><<<gProj, 256>>>(key_,   Wk, bk, (float*)pk, 1.0f);
    mma_gemm<1><<<gProj, 256>>>(value_, Wv, bv, (float*)pv, 1.0f);

    attn_mma<<<dim3(Sc / 64, Hc, Bc), 256>>>(m_it, m_ist, m_df, mask);

    mma_gemm<0><<<gProj, 256>>>((const float*)pctx, Wo, bo, out, 1.0f);
}

// round 15
// speedup vs baseline: 2.1879x; 1.1461x over previous
#include <cuda_runtime.h>
#include <cuda_bf16.h>
#include <cstdint>
#include <math.h>

// Problem constants
#define Bc   8
#define Sc   1024
#define Dc   512
#define Hc   8
#define DKc  64

// Scratch (device globals; no allocations allowed)
// Q/K/V stored PRE-SPLIT as bf16 hi/lo pairs, layout (B,H,S,64).
__device__ __nv_bfloat16 g_qh[Bc * Hc * Sc * DKc];
__device__ __nv_bfloat16 g_ql[Bc * Hc * Sc * DKc];
__device__ __nv_bfloat16 g_kh[Bc * Hc * Sc * DKc];
__device__ __nv_bfloat16 g_kl[Bc * Hc * Sc * DKc];
__device__ __nv_bfloat16 g_vh[Bc * Hc * Sc * DKc];
__device__ __nv_bfloat16 g_vl[Bc * Hc * Sc * DKc];
__device__ float g_ctx[Bc * Sc * Dc];        // (B,S,512)

// ---------------------------------------------------------------------------
// MMA helpers (warp-level HMMA; bf16 inputs, fp32 accumulate)
// ---------------------------------------------------------------------------
__device__ __forceinline__ uint32_t smem_u32(const void* p) {
    return (uint32_t)__cvta_generic_to_shared(p);
}
__device__ __forceinline__ void ldsm_x4(uint32_t& r0, uint32_t& r1,
                                        uint32_t& r2, uint32_t& r3, uint32_t addr) {
    asm volatile("ldmatrix.sync.aligned.m8n8.x4.shared.b16 {%0,%1,%2,%3}, [%4];"
                 : "=r"(r0), "=r"(r1), "=r"(r2), "=r"(r3) : "r"(addr));
}
__device__ __forceinline__ void ldsm_x2(uint32_t& r0, uint32_t& r1, uint32_t addr) {
    asm volatile("ldmatrix.sync.aligned.m8n8.x2.shared.b16 {%0,%1}, [%2];"
                 : "=r"(r0), "=r"(r1) : "r"(addr));
}
__device__ __forceinline__ void ldsm_x2_trans(uint32_t& r0, uint32_t& r1, uint32_t addr) {
    asm volatile("ldmatrix.sync.aligned.m8n8.x2.trans.shared.b16 {%0,%1}, [%2];"
                 : "=r"(r0), "=r"(r1) : "r"(addr));
}
__device__ __forceinline__ void mma_bf16(float* c, const uint32_t* a, const uint32_t* b) {
    asm volatile("mma.sync.aligned.m16n8k16.row.col.f32.bf16.bf16.f32 "
                 "{%0,%1,%2,%3},{%4,%5,%6,%7},{%8,%9},{%0,%1,%2,%3};"
                 : "+f"(c[0]), "+f"(c[1]), "+f"(c[2]), "+f"(c[3])
                 : "r"(a[0]), "r"(a[1]), "r"(a[2]), "r"(a[3]),
                   "r"(b[0]), "r"(b[1]));
}
// split float pair (x=low idx, y=high idx) into packed bf16x2 hi & lo parts
__device__ __forceinline__ void split2(float x, float y, uint32_t& hi, uint32_t& lo) {
    __nv_bfloat16 hx = __float2bfloat16(x), hy = __float2bfloat16(y);
    __nv_bfloat16 lx = __float2bfloat16(x - __bfloat162float(hx));
    __nv_bfloat16 ly = __float2bfloat16(y - __bfloat162float(hy));
    hi = (uint32_t)__bfloat16_as_ushort(hx) | ((uint32_t)__bfloat16_as_ushort(hy) << 16);
    lo = (uint32_t)__bfloat16_as_ushort(lx) | ((uint32_t)__bfloat16_as_ushort(ly) << 16);
}

// ---------------------------------------------------------------------------
// Split-bf16 tensor-core GEMM: out = X*W^T + bias.
// HEADED=1: writes PRE-SPLIT bf16 hi/lo arrays at (B,H,S,64) layout.
// HEADED=0: writes fp32 row-major (final output projection).
// ---------------------------------------------------------------------------
#define BMt  128
#define BNt  128
#define BKt  32
#define PADK 40

template <int HEADED>
__global__ __launch_bounds__(256)
void mma_gemm(const float* __restrict__ X, const float* __restrict__ W,
              const float* __restrict__ bias, float* __restrict__ outF,
              __nv_bfloat16* __restrict__ outH, __nv_bfloat16* __restrict__ outL,
              float scale)
{
    __shared__ __align__(16) __nv_bfloat16 Xh[BMt][PADK];
    __shared__ __align__(16) __nv_bfloat16 Xl[BMt][PADK];
    __shared__ __align__(16) __nv_bfloat16 Wh[BNt][PADK];
    __shared__ __align__(16) __nv_bfloat16 Wl[BNt][PADK];

    const int t    = threadIdx.x;
    const int lane = t & 31;
    const int w    = t >> 5;
    const int wm   = w & 1;
    const int wn   = w >> 1;
    const int m0   = blockIdx.y * BMt;
    const int n0   = blockIdx.x * BNt;

    const int lrow = t >> 1;
    const int lcb  = (t & 1) * 16;

    const int a_row = lane & 15;
    const int a_col = (lane >> 4) * 8;
    const int b_row = lane & 7;
    const int b_col = lane & 8;

    float acc[4][4][4];
#pragma unroll
    for (int i = 0; i < 4; i++)
#pragma unroll
        for (int j = 0; j < 4; j++)
#pragma unroll
            for (int e = 0; e < 4; e++) acc[i][j][e] = 0.0f;

    const float* Xp = X + (size_t)(m0 + lrow) * 512 + lcb;
    const float* Wp = W + (size_t)(n0 + lrow) * 512 + lcb;

    for (int k0 = 0; k0 < 512; k0 += BKt) {
        __syncthreads();
#pragma unroll
        for (int u = 0; u < 4; u++) {
            const int c = lcb + u * 4;
            float4 xv = *(const float4*)(Xp + k0 + u * 4);
            float4 wv = *(const float4*)(Wp + k0 + u * 4);
            uint32_t hi, lo;
            split2(xv.x, xv.y, hi, lo);
            *(uint32_t*)&Xh[lrow][c] = hi;     *(uint32_t*)&Xl[lrow][c] = lo;
            split2(xv.z, xv.w, hi, lo);
            *(uint32_t*)&Xh[lrow][c + 2] = hi; *(uint32_t*)&Xl[lrow][c + 2] = lo;
            split2(wv.x, wv.y, hi, lo);
            *(uint32_t*)&Wh[lrow][c] = hi;     *(uint32_t*)&Wl[lrow][c] = lo;
            split2(wv.z, wv.w, hi, lo);
            *(uint32_t*)&Wh[lrow][c + 2] = hi; *(uint32_t*)&Wl[lrow][c + 2] = lo;
        }
        __syncthreads();

#pragma unroll
        for (int k16 = 0; k16 < BKt; k16 += 16) {
            uint32_t ah[4][4], al[4][4], bh[4][2], bl[4][2];
#pragma unroll
            for (int mt = 0; mt < 4; mt++) {
                const int r = wm * 64 + mt * 16 + a_row;
                ldsm_x4(ah[mt][0], ah[mt][1], ah[mt][2], ah[mt][3],
                        smem_u32(&Xh[r][k16 + a_col]));
                ldsm_x4(al[mt][0], al[mt][1], al[mt][2], al[mt][3],
                        smem_u32(&Xl[r][k16 + a_col]));
            }
#pragma unroll
            for (int nt = 0; nt < 4; nt++) {
                const int r = wn * 32 + nt * 8 + b_row;
                ldsm_x2(bh[nt][0], bh[nt][1], smem_u32(&Wh[r][k16 + b_col]));
                ldsm_x2(bl[nt][0], bl[nt][1], smem_u32(&Wl[r][k16 + b_col]));
            }
#pragma unroll
            for (int mt = 0; mt < 4; mt++)
#pragma unroll
                for (int nt = 0; nt < 4; nt++) {
                    mma_bf16(acc[mt][nt], ah[mt], bh[nt]);
                    mma_bf16(acc[mt][nt], ah[mt], bl[nt]);
                    mma_bf16(acc[mt][nt], al[mt], bh[nt]);
                }
        }
    }

    const int er = lane >> 2;
    const int ec = (lane & 3) * 2;
#pragma unroll
    for (int mt = 0; mt < 4; mt++) {
#pragma unroll
        for (int nt = 0; nt < 4; nt++) {
            const int o = n0 + wn * 32 + nt * 8 + ec;
            const float b0 = bias[o], b1 = bias[o + 1];
#pragma unroll
            for (int half = 0; half < 2; half++) {
                const int m = m0 + wm * 64 + mt * 16 + er + half * 8;
                float rx = (acc[mt][nt][half * 2 + 0] + b0) * scale;
                float ry = (acc[mt][nt][half * 2 + 1] + b1) * scale;
                if (HEADED) {
                    const int h = o >> 6, d = o & 63;
                    const int b = m >> 10, s = m & 1023;
                    const size_t idx = ((size_t)(b * Hc + h) * Sc + s) * DKc + d;
                    uint32_t hi, lo;
                    split2(rx, ry, hi, lo);
                    *(uint32_t*)(outH + idx) = hi;
                    *(uint32_t*)(outL + idx) = lo;
                } else {
                    *(float2*)(outF + (size_t)m * 512 + o) = make_float2(rx, ry);
                }
            }
        }
    }
}

// ---------------------------------------------------------------------------
// Tensor-core flash attention (pre-split inputs). CTA = (b, h, 64 q-rows);
// 256 thr = 8 warps (wm=w&3 -> 16 q-rows, wn=w>>2 -> half of k/d cols).
// k-tile = 32 keys. Staging = pure 16B copies (no conversion math).
// V consumed via ldmatrix.trans from [key][d] (no transpose staging).
// Map/mask prefetched into regs at loop top (hidden behind QK^T MMAs).
// ---------------------------------------------------------------------------
#define KT  32

__global__ __launch_bounds__(256)
void attn_mma(const float* __restrict__ mIntoken,
              const float* __restrict__ mInstat,
              const float* __restrict__ mDataflow,
              const unsigned char* __restrict__ mask)
{
    __shared__ __align__(16) __nv_bfloat16 Kh[32][72], Kl[32][72];   // key x d
    __shared__ __align__(16) __nv_bfloat16 Vh[32][72], Vl[32][72];   // key x d
    __shared__ __align__(16) __nv_bfloat16 Ph[64][40], Pl[64][40];   // q x key
    __shared__ float redmax[2][64], redsum[2][64], marr[64], larr[64];

    const int t    = threadIdx.x;
    const int lane = t & 31;
    const int w    = t >> 5;
    const int wm   = w & 3;    // q band: wm*16
    const int wn   = w >> 2;   // 0..1
    const int q0   = blockIdx.x * 64;
    const int h    = blockIdx.y;
    const int b    = blockIdx.z;

    const int er = lane >> 2;          // fragment row within 8
    const int ec = (lane & 3) * 2;     // fragment col pair
    const int a_row = lane & 15;
    const int a_col = (lane >> 4) * 8;
    const int b_row = lane & 7;
    const int b_col = lane & 8;
    const int t_row = lane & 15;       // ldmatrix.trans source row

    const size_t bh = (size_t)(b * Hc + h);
    const __nv_bfloat16* Qhp = g_qh + (bh * Sc + q0) * DKc;
    const __nv_bfloat16* Qlp = g_ql + (bh * Sc + q0) * DKc;
    const __nv_bfloat16* Khp = g_kh + bh * Sc * DKc;
    const __nv_bfloat16* Klp = g_kl + bh * Sc * DKc;
    const __nv_bfloat16* Vhp = g_vh + bh * Sc * DKc;
    const __nv_bfloat16* Vlp = g_vl + bh * Sc * DKc;

    const int rlo = wm * 16 + er;      // CTA-local q rows this lane owns
    const int rhi = rlo + 8;

    // ---- Q fragments in registers (hi/lo): direct uint32 loads ----
    uint32_t qh[4][4], ql[4][4];
#pragma unroll
    for (int kk = 0; kk < 4; kk++) {
        const int c = kk * 16 + ec;
        qh[kk][0] = *(const uint32_t*)(Qhp + (size_t)rlo * DKc + c);
        qh[kk][1] = *(const uint32_t*)(Qhp + (size_t)rhi * DKc + c);
        qh[kk][2] = *(const uint32_t*)(Qhp + (size_t)rlo * DKc + c + 8);
        qh[kk][3] = *(const uint32_t*)(Qhp + (size_t)rhi * DKc + c + 8);
        ql[kk][0] = *(const uint32_t*)(Qlp + (size_t)rlo * DKc + c);
        ql[kk][1] = *(const uint32_t*)(Qlp + (size_t)rhi * DKc + c);
        ql[kk][2] = *(const uint32_t*)(Qlp + (size_t)rlo * DKc + c + 8);
        ql[kk][3] = *(const uint32_t*)(Qlp + (size_t)rhi * DKc + c + 8);
    }

    if (t < 64) { marr[t] = -INFINITY; larr[t] = 0.0f; }

    const int hg = h >> 1;
    const float* mapB = (hg == 0) ? mIntoken : (hg == 1) ? mInstat
                      : (hg == 2) ? mDataflow : nullptr;
    const float* mr_lo = mapB ? mapB + ((size_t)b * Sc + q0 + rlo) * Sc : nullptr;
    const float* mr_hi = mapB ? mapB + ((size_t)b * Sc + q0 + rhi) * Sc : nullptr;

    float acc[4][4];   // PV accum: 4 d-ntiles x 4
#pragma unroll
    for (int i = 0; i < 4; i++)
#pragma unroll
        for (int j = 0; j < 4; j++) acc[i][j] = 0.0f;

    // staging coords: 32 rows x 8 chunks of 16B per array
    const int s_row = t >> 3;           // 0..31
    const int s_col = (t & 7) * 8;      // bf16 column base

    for (int kt = 0; kt < Sc / KT; kt++) {
        const int k0 = kt * KT;

        // ---- prefetch map + mask into regs (independent of smem) ----
        float2 pf_lo[2], pf_hi[2];
        unsigned char pf_m[4];
#pragma unroll
        for (int nt = 0; nt < 2; nt++) {
            const int cg = k0 + wn * 16 + nt * 8 + ec;
            if (mapB) {
                pf_lo[nt] = *(const float2*)(mr_lo + cg);
                pf_hi[nt] = *(const float2*)(mr_hi + cg);
            }
            const unsigned char* mp = mask + (size_t)b * Sc + cg;
            pf_m[nt * 2 + 0] = mp[0];
            pf_m[nt * 2 + 1] = mp[1];
        }

        __syncthreads();   // prev tile's MMAs done; safe to overwrite smem

        // ---- stage K/V (pure copies, 16B each) ----
        {
            const size_t off = (size_t)(k0 + s_row) * DKc + s_col;
            *(uint4*)&Kh[s_row][s_col] = *(const uint4*)(Khp + off);
            *(uint4*)&Kl[s_row][s_col] = *(const uint4*)(Klp + off);
            *(uint4*)&Vh[s_row][s_col] = *(const uint4*)(Vhp + off);
            *(uint4*)&Vl[s_row][s_col] = *(const uint4*)(Vlp + off);
        }
        __syncthreads();

        // ---- S = Q K^T (fragments) ----
        float s[2][4] = {};
#pragma unroll
        for (int kk = 0; kk < 4; kk++) {
#pragma unroll
            for (int nt = 0; nt < 2; nt++) {
                uint32_t bhv[2], blv[2];
                const int r = wn * 16 + nt * 8 + b_row;
                ldsm_x2(bhv[0], bhv[1], smem_u32(&Kh[r][kk * 16 + b_col]));
                ldsm_x2(blv[0], blv[1], smem_u32(&Kl[r][kk * 16 + b_col]));
                mma_bf16(s[nt], qh[kk], bhv);
                mma_bf16(s[nt], qh[kk], blv);
                mma_bf16(s[nt], ql[kk], bhv);
            }
        }

        // ---- bias maps + mask (prefetched) ----
#pragma unroll
        for (int nt = 0; nt < 2; nt++) {
            if (hg == 0 || hg == 1) {
                s[nt][0] = __fadd_rn(s[nt][0], __fmul_rn(-1.0e9f, pf_lo[nt].x));
                s[nt][1] = __fadd_rn(s[nt][1], __fmul_rn(-1.0e9f, pf_lo[nt].y));
                s[nt][2] = __fadd_rn(s[nt][2], __fmul_rn(-1.0e9f, pf_hi[nt].x));
                s[nt][3] = __fadd_rn(s[nt][3], __fmul_rn(-1.0e9f, pf_hi[nt].y));
            } else if (hg == 2) {
                s[nt][0] = __fmul_rn(s[nt][0], __fadd_rn(1.0f, __fmul_rn(5.0f, pf_lo[nt].x)));
                s[nt][1] = __fmul_rn(s[nt][1], __fadd_rn(1.0f, __fmul_rn(5.0f, pf_lo[nt].y)));
                s[nt][2] = __fmul_rn(s[nt][2], __fadd_rn(1.0f, __fmul_rn(5.0f, pf_hi[nt].x)));
                s[nt][3] = __fmul_rn(s[nt][3], __fadd_rn(1.0f, __fmul_rn(5.0f, pf_hi[nt].y)));
            }
            if (pf_m[nt * 2 + 0]) { s[nt][0] = -1.0e18f; s[nt][2] = -1.0e18f; }
            if (pf_m[nt * 2 + 1]) { s[nt][1] = -1.0e18f; s[nt][3] = -1.0e18f; }
        }

        // ---- row max (warp part) ----
        float mx_lo = fmaxf(fmaxf(s[0][0], s[0][1]), fmaxf(s[1][0], s[1][1]));
        float mx_hi = fmaxf(fmaxf(s[0][2], s[0][3]), fmaxf(s[1][2], s[1][3]));
        mx_lo = fmaxf(mx_lo, __shfl_xor_sync(0xffffffffu, mx_lo, 1));
        mx_lo = fmaxf(mx_lo, __shfl_xor_sync(0xffffffffu, mx_lo, 2));
        mx_hi = fmaxf(mx_hi, __shfl_xor_sync(0xffffffffu, mx_hi, 1));
        mx_hi = fmaxf(mx_hi, __shfl_xor_sync(0xffffffffu, mx_hi, 2));
        if ((lane & 3) == 0) {
            redmax[wn][rlo] = mx_lo;
            redmax[wn][rhi] = mx_hi;
        }
        __syncthreads();

        // ---- online softmax: exp + partial sums + P store ----
        const float mo_lo = marr[rlo], mo_hi = marr[rhi];
        const float tm_lo = fmaxf(redmax[0][rlo], redmax[1][rlo]);
        const float tm_hi = fmaxf(redmax[0][rhi], redmax[1][rhi]);
        const float mn_lo = fmaxf(mo_lo, tm_lo);
        const float mn_hi = fmaxf(mo_hi, tm_hi);
        const float sc_lo = __expf(mo_lo - mn_lo);
        const float sc_hi = __expf(mo_hi - mn_hi);

        float ps_lo = 0.0f, ps_hi = 0.0f;
#pragma unroll
        for (int nt = 0; nt < 2; nt++) {
            float p0 = __expf(s[nt][0] - mn_lo);
            float p1 = __expf(s[nt][1] - mn_lo);
            float p2 = __expf(s[nt][2] - mn_hi);
            float p3 = __expf(s[nt][3] - mn_hi);
            ps_lo += p0 + p1;
            ps_hi += p2 + p3;
            const int cb = wn * 16 + nt * 8 + ec;
            uint32_t hi, lo;
            split2(p0, p1, hi, lo);
            *(uint32_t*)&Ph[rlo][cb] = hi; *(uint32_t*)&Pl[rlo][cb] = lo;
            split2(p2, p3, hi, lo);
            *(uint32_t*)&Ph[rhi][cb] = hi; *(uint32_t*)&Pl[rhi][cb] = lo;
        }
        ps_lo += __shfl_xor_sync(0xffffffffu, ps_lo, 1);
        ps_lo += __shfl_xor_sync(0xffffffffu, ps_lo, 2);
        ps_hi += __shfl_xor_sync(0xffffffffu, ps_hi, 1);
        ps_hi += __shfl_xor_sync(0xffffffffu, ps_hi, 2);
        if ((lane & 3) == 0) {
            redsum[wn][rlo] = ps_lo;
            redsum[wn][rhi] = ps_hi;
        }
        __syncthreads();   // redsum complete; all lanes hold mo/mn/sc in regs

        // l/m update (one owner per row), acc rescale (everyone)
        if (wn == 0 && (lane & 3) == 0) {
            larr[rlo] = larr[rlo] * sc_lo + redsum[0][rlo] + redsum[1][rlo];
            larr[rhi] = larr[rhi] * sc_hi + redsum[0][rhi] + redsum[1][rhi];
            marr[rlo] = mn_lo;
            marr[rhi] = mn_hi;
        }
#pragma unroll
        for (int nt = 0; nt < 4; nt++) {
            acc[nt][0] *= sc_lo; acc[nt][1] *= sc_lo;
            acc[nt][2] *= sc_hi; acc[nt][3] *= sc_hi;
        }

        // ---- acc += P V  (V via ldmatrix.trans from [key][d]) ----
#pragma unroll
        for (int k16 = 0; k16 < KT; k16 += 16) {
            uint32_t pah[4], pal[4];
            ldsm_x4(pah[0], pah[1], pah[2], pah[3],
                    smem_u32(&Ph[wm * 16 + a_row][k16 + a_col]));
            ldsm_x4(pal[0], pal[1], pal[2], pal[3],
                    smem_u32(&Pl[wm * 16 + a_row][k16 + a_col]));
#pragma unroll
            for (int nt = 0; nt < 4; nt++) {
                uint32_t bhv[2], blv[2];
                const int d8 = wn * 32 + nt * 8;
                ldsm_x2_trans(bhv[0], bhv[1], smem_u32(&Vh[k16 + t_row][d8]));
                ldsm_x2_trans(blv[0], blv[1], smem_u32(&Vl[k16 + t_row][d8]));
                mma_bf16(acc[nt], pah, bhv);
                mma_bf16(acc[nt], pah, blv);
                mma_bf16(acc[nt], pal, bhv);
            }
        }
    }

    __syncthreads();   // larr final writes visible
    const float linv_lo = 1.0f / larr[rlo];
    const float linv_hi = 1.0f / larr[rhi];

    // write ctx (B,S,512): row q0+r, col h*64 + (wn*32 + nt*8 + ec)
#pragma unroll
    for (int nt = 0; nt < 4; nt++) {
        const int d = wn * 32 + nt * 8 + ec;
        float2 o0 = make_float2(acc[nt][0] * linv_lo, acc[nt][1] * linv_lo);
        float2 o1 = make_float2(acc[nt][2] * linv_hi, acc[nt][3] * linv_hi);
        *(float2*)(g_ctx + ((size_t)(b * Sc + q0 + rlo)) * Dc + h * DKc + d) = o0;
        *(float2*)(g_ctx + ((size_t)(b * Sc + q0 + rhi)) * Dc + h * DKc + d) = o1;
    }
}

// ---------------------------------------------------------------------------
extern "C" void kernel_launch(void* const* d_in, const int* in_sizes, int n_in,
                              void* d_out, int out_size)
{
    (void)in_sizes; (void)n_in; (void)out_size;
    const float* key_   = (const float*)d_in[0];
    const float* value_ = (const float*)d_in[1];
    const float* query_ = (const float*)d_in[2];
    const float* m_it   = (const float*)d_in[3];
    const float* m_ist  = (const float*)d_in[4];
    const float* m_df   = (const float*)d_in[5];
    const unsigned char* mask = (const unsigned char*)d_in[6];
    const float* Wq = (const float*)d_in[7];
    const float* bq = (const float*)d_in[8];
    const float* Wk = (const float*)d_in[9];
    const float* bk = (const float*)d_in[10];
    const float* Wv = (const float*)d_in[11];
    const float* bv = (const float*)d_in[12];
    const float* Wo = (const float*)d_in[13];
    const float* bo = (const float*)d_in[14];
    float* out = (float*)d_out;

    void *pqh, *pql, *pkh, *pkl, *pvh, *pvl, *pctx;
    cudaGetSymbolAddress(&pqh, g_qh);
    cudaGetSymbolAddress(&pql, g_ql);
    cudaGetSymbolAddress(&pkh, g_kh);
    cudaGetSymbolAddress(&pkl, g_kl);
    cudaGetSymbolAddress(&pvh, g_vh);
    cudaGetSymbolAddress(&pvl, g_vl);
    cudaGetSymbolAddress(&pctx, g_ctx);

    dim3 gProj(Dc / BNt, (Bc * Sc) / BMt);  // (4, 64)
    mma_gemm<1><<<gProj, 256>>>(query_, Wq, bq, nullptr,
                                (__nv_bfloat16*)pqh, (__nv_bfloat16*)pql, 0.125f);
    mma_gemm<1><<<gProj, 256>>>(key_,   Wk, bk, nullptr,
                                (__nv_bfloat16*)pkh, (__nv_bfloat16*)pkl, 1.0f);
    mma_gemm<1><<<gProj, 256>>>(value_, Wv, bv, nullptr,
                                (__nv_bfloat16*)pvh, (__nv_bfloat16*)pvl, 1.0f);

    attn_mma<<<dim3(Sc / 64, Hc, Bc), 256>>>(m_it, m_ist, m_df, mask);

    mma_gemm<0><<<gProj, 256>>>((const float*)pctx, Wo, bo, out,
                                nullptr, nullptr, 1.0f);
}

// round 16
// speedup vs baseline: 2.2544x; 1.0304x over previous
#include <cuda_runtime.h>
#include <cuda_bf16.h>
#include <cstdint>
#include <math.h>

// Problem constants
#define Bc   8
#define Sc   1024
#define Dc   512
#define Hc   8
#define DKc  64

// Scratch (device globals; no allocations allowed)
// Q/K/V stored PRE-SPLIT as bf16 hi/lo pairs, layout (B,H,S,64).
__device__ __nv_bfloat16 g_qh[Bc * Hc * Sc * DKc];
__device__ __nv_bfloat16 g_ql[Bc * Hc * Sc * DKc];
__device__ __nv_bfloat16 g_kh[Bc * Hc * Sc * DKc];
__device__ __nv_bfloat16 g_kl[Bc * Hc * Sc * DKc];
__device__ __nv_bfloat16 g_vh[Bc * Hc * Sc * DKc];
__device__ __nv_bfloat16 g_vl[Bc * Hc * Sc * DKc];
__device__ float g_ctx[Bc * Sc * Dc];        // (B,S,512)

// ---------------------------------------------------------------------------
// MMA / async-copy helpers
// ---------------------------------------------------------------------------
__device__ __forceinline__ uint32_t smem_u32(const void* p) {
    return (uint32_t)__cvta_generic_to_shared(p);
}
__device__ __forceinline__ void ldsm_x4(uint32_t& r0, uint32_t& r1,
                                        uint32_t& r2, uint32_t& r3, uint32_t addr) {
    asm volatile("ldmatrix.sync.aligned.m8n8.x4.shared.b16 {%0,%1,%2,%3}, [%4];"
                 : "=r"(r0), "=r"(r1), "=r"(r2), "=r"(r3) : "r"(addr));
}
__device__ __forceinline__ void ldsm_x2(uint32_t& r0, uint32_t& r1, uint32_t addr) {
    asm volatile("ldmatrix.sync.aligned.m8n8.x2.shared.b16 {%0,%1}, [%2];"
                 : "=r"(r0), "=r"(r1) : "r"(addr));
}
__device__ __forceinline__ void ldsm_x2_trans(uint32_t& r0, uint32_t& r1, uint32_t addr) {
    asm volatile("ldmatrix.sync.aligned.m8n8.x2.trans.shared.b16 {%0,%1}, [%2];"
                 : "=r"(r0), "=r"(r1) : "r"(addr));
}
__device__ __forceinline__ void mma_bf16(float* c, const uint32_t* a, const uint32_t* b) {
    asm volatile("mma.sync.aligned.m16n8k16.row.col.f32.bf16.bf16.f32 "
                 "{%0,%1,%2,%3},{%4,%5,%6,%7},{%8,%9},{%0,%1,%2,%3};"
                 : "+f"(c[0]), "+f"(c[1]), "+f"(c[2]), "+f"(c[3])
                 : "r"(a[0]), "r"(a[1]), "r"(a[2]), "r"(a[3]),
                   "r"(b[0]), "r"(b[1]));
}
__device__ __forceinline__ void cp16(uint32_t dst, const void* src) {
    asm volatile("cp.async.ca.shared.global [%0], [%1], 16;" :: "r"(dst), "l"(src));
}
__device__ __forceinline__ void cp_commit() {
    asm volatile("cp.async.commit_group;");
}
__device__ __forceinline__ void cp_wait0() {
    asm volatile("cp.async.wait_group 0;");
}
// split float pair (x=low idx, y=high idx) into packed bf16x2 hi & lo parts
__device__ __forceinline__ void split2(float x, float y, uint32_t& hi, uint32_t& lo) {
    __nv_bfloat16 hx = __float2bfloat16(x), hy = __float2bfloat16(y);
    __nv_bfloat16 lx = __float2bfloat16(x - __bfloat162float(hx));
    __nv_bfloat16 ly = __float2bfloat16(y - __bfloat162float(hy));
    hi = (uint32_t)__bfloat16_as_ushort(hx) | ((uint32_t)__bfloat16_as_ushort(hy) << 16);
    lo = (uint32_t)__bfloat16_as_ushort(lx) | ((uint32_t)__bfloat16_as_ushort(ly) << 16);
}

// ---------------------------------------------------------------------------
// Split-bf16 tensor-core GEMM (unchanged, known-good): out = X*W^T + bias
// ---------------------------------------------------------------------------
#define BMt  128
#define BNt  128
#define BKt  32
#define PADK 40

template <int HEADED>
__global__ __launch_bounds__(256)
void mma_gemm(const float* __restrict__ X, const float* __restrict__ W,
              const float* __restrict__ bias, float* __restrict__ outF,
              __nv_bfloat16* __restrict__ outH, __nv_bfloat16* __restrict__ outL,
              float scale)
{
    __shared__ __align__(16) __nv_bfloat16 Xh[BMt][PADK];
    __shared__ __align__(16) __nv_bfloat16 Xl[BMt][PADK];
    __shared__ __align__(16) __nv_bfloat16 Wh[BNt][PADK];
    __shared__ __align__(16) __nv_bfloat16 Wl[BNt][PADK];

    const int t    = threadIdx.x;
    const int lane = t & 31;
    const int w    = t >> 5;
    const int wm   = w & 1;
    const int wn   = w >> 1;
    const int m0   = blockIdx.y * BMt;
    const int n0   = blockIdx.x * BNt;

    const int lrow = t >> 1;
    const int lcb  = (t & 1) * 16;

    const int a_row = lane & 15;
    const int a_col = (lane >> 4) * 8;
    const int b_row = lane & 7;
    const int b_col = lane & 8;

    float acc[4][4][4];
#pragma unroll
    for (int i = 0; i < 4; i++)
#pragma unroll
        for (int j = 0; j < 4; j++)
#pragma unroll
            for (int e = 0; e < 4; e++) acc[i][j][e] = 0.0f;

    const float* Xp = X + (size_t)(m0 + lrow) * 512 + lcb;
    const float* Wp = W + (size_t)(n0 + lrow) * 512 + lcb;

    for (int k0 = 0; k0 < 512; k0 += BKt) {
        __syncthreads();
#pragma unroll
        for (int u = 0; u < 4; u++) {
            const int c = lcb + u * 4;
            float4 xv = *(const float4*)(Xp + k0 + u * 4);
            float4 wv = *(const float4*)(Wp + k0 + u * 4);
            uint32_t hi, lo;
            split2(xv.x, xv.y, hi, lo);
            *(uint32_t*)&Xh[lrow][c] = hi;     *(uint32_t*)&Xl[lrow][c] = lo;
            split2(xv.z, xv.w, hi, lo);
            *(uint32_t*)&Xh[lrow][c + 2] = hi; *(uint32_t*)&Xl[lrow][c + 2] = lo;
            split2(wv.x, wv.y, hi, lo);
            *(uint32_t*)&Wh[lrow][c] = hi;     *(uint32_t*)&Wl[lrow][c] = lo;
            split2(wv.z, wv.w, hi, lo);
            *(uint32_t*)&Wh[lrow][c + 2] = hi; *(uint32_t*)&Wl[lrow][c + 2] = lo;
        }
        __syncthreads();

#pragma unroll
        for (int k16 = 0; k16 < BKt; k16 += 16) {
            uint32_t ah[4][4], al[4][4], bh[4][2], bl[4][2];
#pragma unroll
            for (int mt = 0; mt < 4; mt++) {
                const int r = wm * 64 + mt * 16 + a_row;
                ldsm_x4(ah[mt][0], ah[mt][1], ah[mt][2], ah[mt][3],
                        smem_u32(&Xh[r][k16 + a_col]));
                ldsm_x4(al[mt][0], al[mt][1], al[mt][2], al[mt][3],
                        smem_u32(&Xl[r][k16 + a_col]));
            }
#pragma unroll
            for (int nt = 0; nt < 4; nt++) {
                const int r = wn * 32 + nt * 8 + b_row;
                ldsm_x2(bh[nt][0], bh[nt][1], smem_u32(&Wh[r][k16 + b_col]));
                ldsm_x2(bl[nt][0], bl[nt][1], smem_u32(&Wl[r][k16 + b_col]));
            }
#pragma unroll
            for (int mt = 0; mt < 4; mt++)
#pragma unroll
                for (int nt = 0; nt < 4; nt++) {
                    mma_bf16(acc[mt][nt], ah[mt], bh[nt]);
                    mma_bf16(acc[mt][nt], ah[mt], bl[nt]);
                    mma_bf16(acc[mt][nt], al[mt], bh[nt]);
                }
        }
    }

    const int er = lane >> 2;
    const int ec = (lane & 3) * 2;
#pragma unroll
    for (int mt = 0; mt < 4; mt++) {
#pragma unroll
        for (int nt = 0; nt < 4; nt++) {
            const int o = n0 + wn * 32 + nt * 8 + ec;
            const float b0 = bias[o], b1 = bias[o + 1];
#pragma unroll
            for (int half = 0; half < 2; half++) {
                const int m = m0 + wm * 64 + mt * 16 + er + half * 8;
                float rx = (acc[mt][nt][half * 2 + 0] + b0) * scale;
                float ry = (acc[mt][nt][half * 2 + 1] + b1) * scale;
                if (HEADED) {
                    const int h = o >> 6, d = o & 63;
                    const int b = m >> 10, s = m & 1023;
                    const size_t idx = ((size_t)(b * Hc + h) * Sc + s) * DKc + d;
                    uint32_t hi, lo;
                    split2(rx, ry, hi, lo);
                    *(uint32_t*)(outH + idx) = hi;
                    *(uint32_t*)(outL + idx) = lo;
                } else {
                    *(float2*)(outF + (size_t)m * 512 + o) = make_float2(rx, ry);
                }
            }
        }
    }
}

// ---------------------------------------------------------------------------
// Tensor-core flash attention, cp.async DOUBLE-BUFFERED K/V staging.
// CTA = (b, h, 64 q-rows); 256 thr = 8 warps. k-tile = 32 keys.
// Dynamic smem (48.6 KB): Kh/Kl/Vh/Vl x2 bufs, P hi/lo, reductions.
// ---------------------------------------------------------------------------
#define KT  32

// byte offsets into dynamic smem
#define OFF_KH   0                            // [2][32][72] bf16 = 9216
#define OFF_KL   9216
#define OFF_VH   18432
#define OFF_VL   27648
#define OFF_PH   36864                        // [64][40] bf16 = 5120
#define OFF_PL   42240                        // 36864+5120+256 align slack? keep packed:
#undef  OFF_PL
#define OFF_PL   41984
#define OFF_RMAX 47104                        // float[2][64] = 512
#define OFF_RSUM 47616                        // float[2][64] = 512
#define OFF_MARR 48128                        // float[64] = 256
#define OFF_LARR 48384                        // float[64] = 256
#define SMEM_ATTN 48640

__global__ __launch_bounds__(256, 2)
void attn_mma(const float* __restrict__ mIntoken,
              const float* __restrict__ mInstat,
              const float* __restrict__ mDataflow,
              const unsigned char* __restrict__ mask)
{
    extern __shared__ __align__(16) char sm[];
    typedef __nv_bfloat16 (*Tile)[32][72];     // [buf][row][col]
    typedef __nv_bfloat16 (*PTile)[40];        // [row][col]
    Tile  Kh = (Tile)(sm + OFF_KH);
    Tile  Kl = (Tile)(sm + OFF_KL);
    Tile  Vh = (Tile)(sm + OFF_VH);
    Tile  Vl = (Tile)(sm + OFF_VL);
    PTile Ph = (PTile)(sm + OFF_PH);
    PTile Pl = (PTile)(sm + OFF_PL);
    float (*redmax)[64] = (float (*)[64])(sm + OFF_RMAX);
    float (*redsum)[64] = (float (*)[64])(sm + OFF_RSUM);
    float* marr = (float*)(sm + OFF_MARR);
    float* larr = (float*)(sm + OFF_LARR);

    const int t    = threadIdx.x;
    const int lane = t & 31;
    const int w    = t >> 5;
    const int wm   = w & 3;    // q band: wm*16
    const int wn   = w >> 2;   // 0..1
    const int q0   = blockIdx.x * 64;
    const int h    = blockIdx.y;
    const int b    = blockIdx.z;

    const int er = lane >> 2;
    const int ec = (lane & 3) * 2;
    const int a_row = lane & 15;
    const int a_col = (lane >> 4) * 8;
    const int b_row = lane & 7;
    const int b_col = lane & 8;
    const int t_row = lane & 15;

    const size_t bh = (size_t)(b * Hc + h);
    const __nv_bfloat16* Qhp = g_qh + (bh * Sc + q0) * DKc;
    const __nv_bfloat16* Qlp = g_ql + (bh * Sc + q0) * DKc;
    const __nv_bfloat16* Khp = g_kh + bh * Sc * DKc;
    const __nv_bfloat16* Klp = g_kl + bh * Sc * DKc;
    const __nv_bfloat16* Vhp = g_vh + bh * Sc * DKc;
    const __nv_bfloat16* Vlp = g_vl + bh * Sc * DKc;

    const int rlo = wm * 16 + er;
    const int rhi = rlo + 8;

    // staging coords: 32 rows x 8 chunks of 16B per array
    const int s_row = t >> 3;
    const int s_col = (t & 7) * 8;
    const size_t s_base = (size_t)s_row * DKc + s_col;

    // ---- preload tile 0 into buffer 0 ----
    cp16(smem_u32(&Kh[0][s_row][s_col]), Khp + s_base);
    cp16(smem_u32(&Kl[0][s_row][s_col]), Klp + s_base);
    cp16(smem_u32(&Vh[0][s_row][s_col]), Vhp + s_base);
    cp16(smem_u32(&Vl[0][s_row][s_col]), Vlp + s_base);
    cp_commit();

    // ---- Q fragments in registers (hi/lo) ----
    uint32_t qh[4][4], ql[4][4];
#pragma unroll
    for (int kk = 0; kk < 4; kk++) {
        const int c = kk * 16 + ec;
        qh[kk][0] = *(const uint32_t*)(Qhp + (size_t)rlo * DKc + c);
        qh[kk][1] = *(const uint32_t*)(Qhp + (size_t)rhi * DKc + c);
        qh[kk][2] = *(const uint32_t*)(Qhp + (size_t)rlo * DKc + c + 8);
        qh[kk][3] = *(const uint32_t*)(Qhp + (size_t)rhi * DKc + c + 8);
        ql[kk][0] = *(const uint32_t*)(Qlp + (size_t)rlo * DKc + c);
        ql[kk][1] = *(const uint32_t*)(Qlp + (size_t)rhi * DKc + c);
        ql[kk][2] = *(const uint32_t*)(Qlp + (size_t)rlo * DKc + c + 8);
        ql[kk][3] = *(const uint32_t*)(Qlp + (size_t)rhi * DKc + c + 8);
    }

    if (t < 64) { marr[t] = -INFINITY; larr[t] = 0.0f; }

    const int hg = h >> 1;
    const float* mapB = (hg == 0) ? mIntoken : (hg == 1) ? mInstat
                      : (hg == 2) ? mDataflow : nullptr;
    const float* mr_lo = mapB ? mapB + ((size_t)b * Sc + q0 + rlo) * Sc : nullptr;
    const float* mr_hi = mapB ? mapB + ((size_t)b * Sc + q0 + rhi) * Sc : nullptr;

    float acc[4][4];
#pragma unroll
    for (int i = 0; i < 4; i++)
#pragma unroll
        for (int j = 0; j < 4; j++) acc[i][j] = 0.0f;

    for (int kt = 0; kt < Sc / KT; kt++) {
        const int k0 = kt * KT;
        const int buf = kt & 1;

        // ---- prefetch map + mask into regs ----
        float2 pf_lo[2], pf_hi[2];
        unsigned char pf_m[4];
#pragma unroll
        for (int nt = 0; nt < 2; nt++) {
            const int cg = k0 + wn * 16 + nt * 8 + ec;
            if (mapB) {
                pf_lo[nt] = *(const float2*)(mr_lo + cg);
                pf_hi[nt] = *(const float2*)(mr_hi + cg);
            }
            const unsigned char* mp = mask + (size_t)b * Sc + cg;
            pf_m[nt * 2 + 0] = mp[0];
            pf_m[nt * 2 + 1] = mp[1];
        }

        cp_wait0();          // tile kt resident in buf
        __syncthreads();     // visible to all; prev iter's P/acc reads done

        // ---- issue tile kt+1 into other buffer (overlaps compute) ----
        if (kt + 1 < Sc / KT) {
            const size_t off = (size_t)(KT) * DKc + (size_t)kt * KT * DKc + s_base;
            const int nb = buf ^ 1;
            cp16(smem_u32(&Kh[nb][s_row][s_col]), Khp + off);
            cp16(smem_u32(&Kl[nb][s_row][s_col]), Klp + off);
            cp16(smem_u32(&Vh[nb][s_row][s_col]), Vhp + off);
            cp16(smem_u32(&Vl[nb][s_row][s_col]), Vlp + off);
        }
        cp_commit();         // empty group when no issue (keeps wait_group 0 correct)

        // ---- S = Q K^T ----
        float s[2][4] = {};
#pragma unroll
        for (int kk = 0; kk < 4; kk++) {
#pragma unroll
            for (int nt = 0; nt < 2; nt++) {
                uint32_t bhv[2], blv[2];
                const int r = wn * 16 + nt * 8 + b_row;
                ldsm_x2(bhv[0], bhv[1], smem_u32(&Kh[buf][r][kk * 16 + b_col]));
                ldsm_x2(blv[0], blv[1], smem_u32(&Kl[buf][r][kk * 16 + b_col]));
                mma_bf16(s[nt], qh[kk], bhv);
                mma_bf16(s[nt], qh[kk], blv);
                mma_bf16(s[nt], ql[kk], bhv);
            }
        }

        // ---- bias maps + mask (prefetched) ----
#pragma unroll
        for (int nt = 0; nt < 2; nt++) {
            if (hg == 0 || hg == 1) {
                s[nt][0] = __fadd_rn(s[nt][0], __fmul_rn(-1.0e9f, pf_lo[nt].x));
                s[nt][1] = __fadd_rn(s[nt][1], __fmul_rn(-1.0e9f, pf_lo[nt].y));
                s[nt][2] = __fadd_rn(s[nt][2], __fmul_rn(-1.0e9f, pf_hi[nt].x));
                s[nt][3] = __fadd_rn(s[nt][3], __fmul_rn(-1.0e9f, pf_hi[nt].y));
            } else if (hg == 2) {
                s[nt][0] = __fmul_rn(s[nt][0], __fadd_rn(1.0f, __fmul_rn(5.0f, pf_lo[nt].x)));
                s[nt][1] = __fmul_rn(s[nt][1], __fadd_rn(1.0f, __fmul_rn(5.0f, pf_lo[nt].y)));
                s[nt][2] = __fmul_rn(s[nt][2], __fadd_rn(1.0f, __fmul_rn(5.0f, pf_hi[nt].x)));
                s[nt][3] = __fmul_rn(s[nt][3], __fadd_rn(1.0f, __fmul_rn(5.0f, pf_hi[nt].y)));
            }
            if (pf_m[nt * 2 + 0]) { s[nt][0] = -1.0e18f; s[nt][2] = -1.0e18f; }
            if (pf_m[nt * 2 + 1]) { s[nt][1] = -1.0e18f; s[nt][3] = -1.0e18f; }
        }

        // ---- row max (warp part) ----
        float mx_lo = fmaxf(fmaxf(s[0][0], s[0][1]), fmaxf(s[1][0], s[1][1]));
        float mx_hi = fmaxf(fmaxf(s[0][2], s[0][3]), fmaxf(s[1][2], s[1][3]));
        mx_lo = fmaxf(mx_lo, __shfl_xor_sync(0xffffffffu, mx_lo, 1));
        mx_lo = fmaxf(mx_lo, __shfl_xor_sync(0xffffffffu, mx_lo, 2));
        mx_hi = fmaxf(mx_hi, __shfl_xor_sync(0xffffffffu, mx_hi, 1));
        mx_hi = fmaxf(mx_hi, __shfl_xor_sync(0xffffffffu, mx_hi, 2));
        if ((lane & 3) == 0) {
            redmax[wn][rlo] = mx_lo;
            redmax[wn][rhi] = mx_hi;
        }
        __syncthreads();

        // ---- online softmax ----
        const float mo_lo = marr[rlo], mo_hi = marr[rhi];
        const float tm_lo = fmaxf(redmax[0][rlo], redmax[1][rlo]);
        const float tm_hi = fmaxf(redmax[0][rhi], redmax[1][rhi]);
        const float mn_lo = fmaxf(mo_lo, tm_lo);
        const float mn_hi = fmaxf(mo_hi, tm_hi);
        const float sc_lo = __expf(mo_lo - mn_lo);
        const float sc_hi = __expf(mo_hi - mn_hi);

        float ps_lo = 0.0f, ps_hi = 0.0f;
#pragma unroll
        for (int nt = 0; nt < 2; nt++) {
            float p0 = __expf(s[nt][0] - mn_lo);
            float p1 = __expf(s[nt][1] - mn_lo);
            float p2 = __expf(s[nt][2] - mn_hi);
            float p3 = __expf(s[nt][3] - mn_hi);
            ps_lo += p0 + p1;
            ps_hi += p2 + p3;
            const int cb = wn * 16 + nt * 8 + ec;
            uint32_t hi, lo;
            split2(p0, p1, hi, lo);
            *(uint32_t*)&Ph[rlo][cb] = hi; *(uint32_t*)&Pl[rlo][cb] = lo;
            split2(p2, p3, hi, lo);
            *(uint32_t*)&Ph[rhi][cb] = hi; *(uint32_t*)&Pl[rhi][cb] = lo;
        }
        ps_lo += __shfl_xor_sync(0xffffffffu, ps_lo, 1);
        ps_lo += __shfl_xor_sync(0xffffffffu, ps_lo, 2);
        ps_hi += __shfl_xor_sync(0xffffffffu, ps_hi, 1);
        ps_hi += __shfl_xor_sync(0xffffffffu, ps_hi, 2);
        if ((lane & 3) == 0) {
            redsum[wn][rlo] = ps_lo;
            redsum[wn][rhi] = ps_hi;
        }
        __syncthreads();

        if (wn == 0 && (lane & 3) == 0) {
            larr[rlo] = larr[rlo] * sc_lo + redsum[0][rlo] + redsum[1][rlo];
            larr[rhi] = larr[rhi] * sc_hi + redsum[0][rhi] + redsum[1][rhi];
            marr[rlo] = mn_lo;
            marr[rhi] = mn_hi;
        }
#pragma unroll
        for (int nt = 0; nt < 4; nt++) {
            acc[nt][0] *= sc_lo; acc[nt][1] *= sc_lo;
            acc[nt][2] *= sc_hi; acc[nt][3] *= sc_hi;
        }

        // ---- acc += P V  (V via ldmatrix.trans from [key][d]) ----
#pragma unroll
        for (int k16 = 0; k16 < KT; k16 += 16) {
            uint32_t pah[4], pal[4];
            ldsm_x4(pah[0], pah[1], pah[2], pah[3],
                    smem_u32(&Ph[wm * 16 + a_row][k16 + a_col]));
            ldsm_x4(pal[0], pal[1], pal[2], pal[3],
                    smem_u32(&Pl[wm * 16 + a_row][k16 + a_col]));
#pragma unroll
            for (int nt = 0; nt < 4; nt++) {
                uint32_t bhv[2], blv[2];
                const int d8 = wn * 32 + nt * 8;
                ldsm_x2_trans(bhv[0], bhv[1], smem_u32(&Vh[buf][k16 + t_row][d8]));
                ldsm_x2_trans(blv[0], blv[1], smem_u32(&Vl[buf][k16 + t_row][d8]));
                mma_bf16(acc[nt], pah, bhv);
                mma_bf16(acc[nt], pah, blv);
                mma_bf16(acc[nt], pal, bhv);
            }
        }
    }

    __syncthreads();
    const float linv_lo = 1.0f / larr[rlo];
    const float linv_hi = 1.0f / larr[rhi];

#pragma unroll
    for (int nt = 0; nt < 4; nt++) {
        const int d = wn * 32 + nt * 8 + ec;
        float2 o0 = make_float2(acc[nt][0] * linv_lo, acc[nt][1] * linv_lo);
        float2 o1 = make_float2(acc[nt][2] * linv_hi, acc[nt][3] * linv_hi);
        *(float2*)(g_ctx + ((size_t)(b * Sc + q0 + rlo)) * Dc + h * DKc + d) = o0;
        *(float2*)(g_ctx + ((size_t)(b * Sc + q0 + rhi)) * Dc + h * DKc + d) = o1;
    }
}

// ---------------------------------------------------------------------------
extern "C" void kernel_launch(void* const* d_in, const int* in_sizes, int n_in,
                              void* d_out, int out_size)
{
    (void)in_sizes; (void)n_in; (void)out_size;
    const float* key_   = (const float*)d_in[0];
    const float* value_ = (const float*)d_in[1];
    const float* query_ = (const float*)d_in[2];
    const float* m_it   = (const float*)d_in[3];
    const float* m_ist  = (const float*)d_in[4];
    const float* m_df   = (const float*)d_in[5];
    const unsigned char* mask = (const unsigned char*)d_in[6];
    const float* Wq = (const float*)d_in[7];
    const float* bq = (const float*)d_in[8];
    const float* Wk = (const float*)d_in[9];
    const float* bk = (const float*)d_in[10];
    const float* Wv = (const float*)d_in[11];
    const float* bv = (const float*)d_in[12];
    const float* Wo = (const float*)d_in[13];
    const float* bo = (const float*)d_in[14];
    float* out = (float*)d_out;

    void *pqh, *pql, *pkh, *pkl, *pvh, *pvl, *pctx;
    cudaGetSymbolAddress(&pqh, g_qh);
    cudaGetSymbolAddress(&pql, g_ql);
    cudaGetSymbolAddress(&pkh, g_kh);
    cudaGetSymbolAddress(&pkl, g_kl);
    cudaGetSymbolAddress(&pvh, g_vh);
    cudaGetSymbolAddress(&pvl, g_vl);
    cudaGetSymbolAddress(&pctx, g_ctx);

    static int smem_set = 0;
    if (!smem_set) {
        cudaFuncSetAttribute(attn_mma,
                             cudaFuncAttributeMaxDynamicSharedMemorySize, SMEM_ATTN);
        smem_set = 1;
    }

    dim3 gProj(Dc / BNt, (Bc * Sc) / BMt);  // (4, 64)
    mma_gemm<1><<<gProj, 256>>>(query_, Wq, bq, nullptr,
                                (__nv_bfloat16*)pqh, (__nv_bfloat16*)pql, 0.125f);
    mma_gemm<1><<<gProj, 256>>>(key_,   Wk, bk, nullptr,
                                (__nv_bfloat16*)pkh, (__nv_bfloat16*)pkl, 1.0f);
    mma_gemm<1><<<gProj, 256>>>(value_, Wv, bv, nullptr,
                                (__nv_bfloat16*)pvh, (__nv_bfloat16*)pvl, 1.0f);

    attn_mma<<<dim3(Sc / 64, Hc, Bc), 256, SMEM_ATTN>>>(m_it, m_ist, m_df, mask);

    mma_gemm<0><<<gProj, 256>>>((const float*)pctx, Wo, bo, out,
                                nullptr, nullptr, 1.0f);
}

// round 17
// speedup vs baseline: 2.4764x; 1.0984x over previous
#include <cuda_runtime.h>
#include <cuda_bf16.h>
#include <cstdint>
#include <math.h>

// Problem constants
#define Bc   8
#define Sc   1024
#define Dc   512
#define Hc   8
#define DKc  64

// Scratch (device globals; no allocations allowed)
// Q/K/V stored PRE-SPLIT as bf16 hi/lo pairs, layout (B,H,S,64).
__device__ __nv_bfloat16 g_qh[Bc * Hc * Sc * DKc];
__device__ __nv_bfloat16 g_ql[Bc * Hc * Sc * DKc];
__device__ __nv_bfloat16 g_kh[Bc * Hc * Sc * DKc];
__device__ __nv_bfloat16 g_kl[Bc * Hc * Sc * DKc];
__device__ __nv_bfloat16 g_vh[Bc * Hc * Sc * DKc];
__device__ __nv_bfloat16 g_vl[Bc * Hc * Sc * DKc];
__device__ float g_ctx[Bc * Sc * Dc];        // (B,S,512)

// ---------------------------------------------------------------------------
// MMA / async-copy helpers
// ---------------------------------------------------------------------------
__device__ __forceinline__ uint32_t smem_u32(const void* p) {
    return (uint32_t)__cvta_generic_to_shared(p);
}
__device__ __forceinline__ void ldsm_x4(uint32_t& r0, uint32_t& r1,
                                        uint32_t& r2, uint32_t& r3, uint32_t addr) {
    asm volatile("ldmatrix.sync.aligned.m8n8.x4.shared.b16 {%0,%1,%2,%3}, [%4];"
                 : "=r"(r0), "=r"(r1), "=r"(r2), "=r"(r3) : "r"(addr));
}
__device__ __forceinline__ void ldsm_x2(uint32_t& r0, uint32_t& r1, uint32_t addr) {
    asm volatile("ldmatrix.sync.aligned.m8n8.x2.shared.b16 {%0,%1}, [%2];"
                 : "=r"(r0), "=r"(r1) : "r"(addr));
}
__device__ __forceinline__ void ldsm_x4_trans(uint32_t& r0, uint32_t& r1,
                                              uint32_t& r2, uint32_t& r3, uint32_t addr) {
    asm volatile("ldmatrix.sync.aligned.m8n8.x4.trans.shared.b16 {%0,%1,%2,%3}, [%4];"
                 : "=r"(r0), "=r"(r1), "=r"(r2), "=r"(r3) : "r"(addr));
}
__device__ __forceinline__ void mma_bf16(float* c, const uint32_t* a, const uint32_t* b) {
    asm volatile("mma.sync.aligned.m16n8k16.row.col.f32.bf16.bf16.f32 "
                 "{%0,%1,%2,%3},{%4,%5,%6,%7},{%8,%9},{%0,%1,%2,%3};"
                 : "+f"(c[0]), "+f"(c[1]), "+f"(c[2]), "+f"(c[3])
                 : "r"(a[0]), "r"(a[1]), "r"(a[2]), "r"(a[3]),
                   "r"(b[0]), "r"(b[1]));
}
__device__ __forceinline__ void cp16(uint32_t dst, const void* src) {
    asm volatile("cp.async.ca.shared.global [%0], [%1], 16;" :: "r"(dst), "l"(src));
}
__device__ __forceinline__ void cp_commit() {
    asm volatile("cp.async.commit_group;");
}
__device__ __forceinline__ void cp_wait0() {
    asm volatile("cp.async.wait_group 0;");
}
// split float pair (x=low idx, y=high idx) into packed bf16x2 hi & lo parts
__device__ __forceinline__ void split2(float x, float y, uint32_t& hi, uint32_t& lo) {
    __nv_bfloat16 hx = __float2bfloat16(x), hy = __float2bfloat16(y);
    __nv_bfloat16 lx = __float2bfloat16(x - __bfloat162float(hx));
    __nv_bfloat16 ly = __float2bfloat16(y - __bfloat162float(hy));
    hi = (uint32_t)__bfloat16_as_ushort(hx) | ((uint32_t)__bfloat16_as_ushort(hy) << 16);
    lo = (uint32_t)__bfloat16_as_ushort(lx) | ((uint32_t)__bfloat16_as_ushort(ly) << 16);
}

// ---------------------------------------------------------------------------
// Split-bf16 tensor-core GEMM (unchanged, known-good): out = X*W^T + bias
// ---------------------------------------------------------------------------
#define BMt  128
#define BNt  128
#define BKt  32
#define PADK 40

template <int HEADED>
__global__ __launch_bounds__(256)
void mma_gemm(const float* __restrict__ X, const float* __restrict__ W,
              const float* __restrict__ bias, float* __restrict__ outF,
              __nv_bfloat16* __restrict__ outH, __nv_bfloat16* __restrict__ outL,
              float scale)
{
    __shared__ __align__(16) __nv_bfloat16 Xh[BMt][PADK];
    __shared__ __align__(16) __nv_bfloat16 Xl[BMt][PADK];
    __shared__ __align__(16) __nv_bfloat16 Wh[BNt][PADK];
    __shared__ __align__(16) __nv_bfloat16 Wl[BNt][PADK];

    const int t    = threadIdx.x;
    const int lane = t & 31;
    const int w    = t >> 5;
    const int wm   = w & 1;
    const int wn   = w >> 1;
    const int m0   = blockIdx.y * BMt;
    const int n0   = blockIdx.x * BNt;

    const int lrow = t >> 1;
    const int lcb  = (t & 1) * 16;

    const int a_row = lane & 15;
    const int a_col = (lane >> 4) * 8;
    const int b_row = lane & 7;
    const int b_col = lane & 8;

    float acc[4][4][4];
#pragma unroll
    for (int i = 0; i < 4; i++)
#pragma unroll
        for (int j = 0; j < 4; j++)
#pragma unroll
            for (int e = 0; e < 4; e++) acc[i][j][e] = 0.0f;

    const float* Xp = X + (size_t)(m0 + lrow) * 512 + lcb;
    const float* Wp = W + (size_t)(n0 + lrow) * 512 + lcb;

    for (int k0 = 0; k0 < 512; k0 += BKt) {
        __syncthreads();
#pragma unroll
        for (int u = 0; u < 4; u++) {
            const int c = lcb + u * 4;
            float4 xv = *(const float4*)(Xp + k0 + u * 4);
            float4 wv = *(const float4*)(Wp + k0 + u * 4);
            uint32_t hi, lo;
            split2(xv.x, xv.y, hi, lo);
            *(uint32_t*)&Xh[lrow][c] = hi;     *(uint32_t*)&Xl[lrow][c] = lo;
            split2(xv.z, xv.w, hi, lo);
            *(uint32_t*)&Xh[lrow][c + 2] = hi; *(uint32_t*)&Xl[lrow][c + 2] = lo;
            split2(wv.x, wv.y, hi, lo);
            *(uint32_t*)&Wh[lrow][c] = hi;     *(uint32_t*)&Wl[lrow][c] = lo;
            split2(wv.z, wv.w, hi, lo);
            *(uint32_t*)&Wh[lrow][c + 2] = hi; *(uint32_t*)&Wl[lrow][c + 2] = lo;
        }
        __syncthreads();

#pragma unroll
        for (int k16 = 0; k16 < BKt; k16 += 16) {
            uint32_t ah[4][4], al[4][4], bh[4][2], bl[4][2];
#pragma unroll
            for (int mt = 0; mt < 4; mt++) {
                const int r = wm * 64 + mt * 16 + a_row;
                ldsm_x4(ah[mt][0], ah[mt][1], ah[mt][2], ah[mt][3],
                        smem_u32(&Xh[r][k16 + a_col]));
                ldsm_x4(al[mt][0], al[mt][1], al[mt][2], al[mt][3],
                        smem_u32(&Xl[r][k16 + a_col]));
            }
#pragma unroll
            for (int nt = 0; nt < 4; nt++) {
                const int r = wn * 32 + nt * 8 + b_row;
                ldsm_x2(bh[nt][0], bh[nt][1], smem_u32(&Wh[r][k16 + b_col]));
                ldsm_x2(bl[nt][0], bl[nt][1], smem_u32(&Wl[r][k16 + b_col]));
            }
#pragma unroll
            for (int mt = 0; mt < 4; mt++)
#pragma unroll
                for (int nt = 0; nt < 4; nt++) {
                    mma_bf16(acc[mt][nt], ah[mt], bh[nt]);
                    mma_bf16(acc[mt][nt], ah[mt], bl[nt]);
                    mma_bf16(acc[mt][nt], al[mt], bh[nt]);
                }
        }
    }

    const int er = lane >> 2;
    const int ec = (lane & 3) * 2;
#pragma unroll
    for (int mt = 0; mt < 4; mt++) {
#pragma unroll
        for (int nt = 0; nt < 4; nt++) {
            const int o = n0 + wn * 32 + nt * 8 + ec;
            const float b0 = bias[o], b1 = bias[o + 1];
#pragma unroll
            for (int half = 0; half < 2; half++) {
                const int m = m0 + wm * 64 + mt * 16 + er + half * 8;
                float rx = (acc[mt][nt][half * 2 + 0] + b0) * scale;
                float ry = (acc[mt][nt][half * 2 + 1] + b1) * scale;
                if (HEADED) {
                    const int h = o >> 6, d = o & 63;
                    const int b = m >> 10, s = m & 1023;
                    const size_t idx = ((size_t)(b * Hc + h) * Sc + s) * DKc + d;
                    uint32_t hi, lo;
                    split2(rx, ry, hi, lo);
                    *(uint32_t*)(outH + idx) = hi;
                    *(uint32_t*)(outL + idx) = lo;
                } else {
                    *(float2*)(outF + (size_t)m * 512 + o) = make_float2(rx, ry);
                }
            }
        }
    }
}

// ---------------------------------------------------------------------------
// Register-resident flash attention. CTA = (b, h, 128 q-rows); 8 warps;
// warp w owns q-rows w*16..w*16+15 and ALL 32 keys of each tile.
// Softmax entirely in registers (quad shuffles); P packed from S fragments
// directly into A-fragments (no smem round trip). 1 barrier per tile.
// K/V double-buffered via cp.async.
// ---------------------------------------------------------------------------
#define KT  32
#define QROWS 128

__global__ __launch_bounds__(256, 2)
void attn_mma(const float* __restrict__ mIntoken,
              const float* __restrict__ mInstat,
              const float* __restrict__ mDataflow,
              const unsigned char* __restrict__ mask)
{
    __shared__ __align__(16) __nv_bfloat16 Kh[2][32][72], Kl[2][32][72];
    __shared__ __align__(16) __nv_bfloat16 Vh[2][32][72], Vl[2][32][72];

    const int t    = threadIdx.x;
    const int lane = t & 31;
    const int w    = t >> 5;          // 0..7: q band w*16
    const int q0   = blockIdx.x * QROWS;
    const int h    = blockIdx.y;
    const int b    = blockIdx.z;

    const int er = lane >> 2;
    const int ec = (lane & 3) * 2;

    // ldmatrix.x4 addressing for K (B-operand, 2 n-tiles per load)
    const int k_r4 = (lane & 7) + ((lane & 16) >> 1);  // key row within pair
    const int k_c4 = lane & 8;                          // col half
    // ldmatrix.x4.trans addressing for V (2 d-groups per load)
    const int v_r4 = lane & 15;                         // key row
    const int v_c4 = (lane & 16) >> 1;                  // d offset (0 or 8)

    const size_t bh = (size_t)(b * Hc + h);
    const __nv_bfloat16* Qhp = g_qh + (bh * Sc + q0) * DKc;
    const __nv_bfloat16* Qlp = g_ql + (bh * Sc + q0) * DKc;
    const __nv_bfloat16* Khp = g_kh + bh * Sc * DKc;
    const __nv_bfloat16* Klp = g_kl + bh * Sc * DKc;
    const __nv_bfloat16* Vhp = g_vh + bh * Sc * DKc;
    const __nv_bfloat16* Vlp = g_vl + bh * Sc * DKc;

    const int rlo = w * 16 + er;      // CTA-local q rows this lane owns
    const int rhi = rlo + 8;

    // staging coords: 32 rows x 8 chunks of 16B
    const int s_row = t >> 3;
    const int s_col = (t & 7) * 8;
    const size_t s_base = (size_t)s_row * DKc + s_col;

    // ---- preload tile 0 into buffer 0 ----
    cp16(smem_u32(&Kh[0][s_row][s_col]), Khp + s_base);
    cp16(smem_u32(&Kl[0][s_row][s_col]), Klp + s_base);
    cp16(smem_u32(&Vh[0][s_row][s_col]), Vhp + s_base);
    cp16(smem_u32(&Vl[0][s_row][s_col]), Vlp + s_base);
    cp_commit();

    // ---- Q fragments in registers (hi/lo) ----
    uint32_t qfh[4][4], qfl[4][4];
#pragma unroll
    for (int kk = 0; kk < 4; kk++) {
        const int c = kk * 16 + ec;
        qfh[kk][0] = *(const uint32_t*)(Qhp + (size_t)rlo * DKc + c);
        qfh[kk][1] = *(const uint32_t*)(Qhp + (size_t)rhi * DKc + c);
        qfh[kk][2] = *(const uint32_t*)(Qhp + (size_t)rlo * DKc + c + 8);
        qfh[kk][3] = *(const uint32_t*)(Qhp + (size_t)rhi * DKc + c + 8);
        qfl[kk][0] = *(const uint32_t*)(Qlp + (size_t)rlo * DKc + c);
        qfl[kk][1] = *(const uint32_t*)(Qlp + (size_t)rhi * DKc + c);
        qfl[kk][2] = *(const uint32_t*)(Qlp + (size_t)rlo * DKc + c + 8);
        qfl[kk][3] = *(const uint32_t*)(Qlp + (size_t)rhi * DKc + c + 8);
    }

    const int hg = h >> 1;
    const float* mapB = (hg == 0) ? mIntoken : (hg == 1) ? mInstat
                      : (hg == 2) ? mDataflow : nullptr;
    const float* mr_lo = mapB ? mapB + ((size_t)b * Sc + q0 + rlo) * Sc : nullptr;
    const float* mr_hi = mapB ? mapB + ((size_t)b * Sc + q0 + rhi) * Sc : nullptr;

    // per-lane online-softmax state (rows rlo, rhi) + PV accumulators (64 d)
    float m_lo = -INFINITY, m_hi = -INFINITY, l_lo = 0.0f, l_hi = 0.0f;
    float acc[8][4];
#pragma unroll
    for (int i = 0; i < 8; i++)
#pragma unroll
        for (int j = 0; j < 4; j++) acc[i][j] = 0.0f;

    for (int kt = 0; kt < Sc / KT; kt++) {
        const int k0 = kt * KT;
        const int buf = kt & 1;

        // ---- prefetch map + mask into regs ----
        float2 pf_lo[4], pf_hi[4];
        unsigned char pf_m[8];
#pragma unroll
        for (int nt = 0; nt < 4; nt++) {
            const int cg = k0 + nt * 8 + ec;
            if (mapB) {
                pf_lo[nt] = *(const float2*)(mr_lo + cg);
                pf_hi[nt] = *(const float2*)(mr_hi + cg);
            }
            const unsigned char* mp = mask + (size_t)b * Sc + cg;
            pf_m[nt * 2 + 0] = mp[0];
            pf_m[nt * 2 + 1] = mp[1];
        }

        cp_wait0();
        __syncthreads();    // tile kt visible; all warps done with other buffer

        // ---- issue tile kt+1 into other buffer ----
        if (kt + 1 < Sc / KT) {
            const size_t off = (size_t)(kt + 1) * KT * DKc + s_base;
            const int nb = buf ^ 1;
            cp16(smem_u32(&Kh[nb][s_row][s_col]), Khp + off);
            cp16(smem_u32(&Kl[nb][s_row][s_col]), Klp + off);
            cp16(smem_u32(&Vh[nb][s_row][s_col]), Vhp + off);
            cp16(smem_u32(&Vl[nb][s_row][s_col]), Vlp + off);
        }
        cp_commit();

        // ---- S = Q K^T : 16 rows x 32 keys per warp ----
        float s[4][4] = {};
#pragma unroll
        for (int kk = 0; kk < 4; kk++) {
#pragma unroll
            for (int np = 0; np < 2; np++) {     // n-tile pairs: keys np*16
                uint32_t bhv[4], blv[4];
                ldsm_x4(bhv[0], bhv[1], bhv[2], bhv[3],
                        smem_u32(&Kh[buf][np * 16 + k_r4][kk * 16 + k_c4]));
                ldsm_x4(blv[0], blv[1], blv[2], blv[3],
                        smem_u32(&Kl[buf][np * 16 + k_r4][kk * 16 + k_c4]));
                mma_bf16(s[np * 2 + 0], qfh[kk], bhv + 0);
                mma_bf16(s[np * 2 + 0], qfh[kk], blv + 0);
                mma_bf16(s[np * 2 + 0], qfl[kk], bhv + 0);
                mma_bf16(s[np * 2 + 1], qfh[kk], bhv + 2);
                mma_bf16(s[np * 2 + 1], qfh[kk], blv + 2);
                mma_bf16(s[np * 2 + 1], qfl[kk], bhv + 2);
            }
        }

        // ---- bias maps + mask ----
#pragma unroll
        for (int nt = 0; nt < 4; nt++) {
            if (hg == 0 || hg == 1) {
                s[nt][0] = __fadd_rn(s[nt][0], __fmul_rn(-1.0e9f, pf_lo[nt].x));
                s[nt][1] = __fadd_rn(s[nt][1], __fmul_rn(-1.0e9f, pf_lo[nt].y));
                s[nt][2] = __fadd_rn(s[nt][2], __fmul_rn(-1.0e9f, pf_hi[nt].x));
                s[nt][3] = __fadd_rn(s[nt][3], __fmul_rn(-1.0e9f, pf_hi[nt].y));
            } else if (hg == 2) {
                s[nt][0] = __fmul_rn(s[nt][0], __fadd_rn(1.0f, __fmul_rn(5.0f, pf_lo[nt].x)));
                s[nt][1] = __fmul_rn(s[nt][1], __fadd_rn(1.0f, __fmul_rn(5.0f, pf_lo[nt].y)));
                s[nt][2] = __fmul_rn(s[nt][2], __fadd_rn(1.0f, __fmul_rn(5.0f, pf_hi[nt].x)));
                s[nt][3] = __fmul_rn(s[nt][3], __fadd_rn(1.0f, __fmul_rn(5.0f, pf_hi[nt].y)));
            }
            if (pf_m[nt * 2 + 0]) { s[nt][0] = -1.0e18f; s[nt][2] = -1.0e18f; }
            if (pf_m[nt * 2 + 1]) { s[nt][1] = -1.0e18f; s[nt][3] = -1.0e18f; }
        }

        // ---- row max: local over 4 n-tiles + quad shuffle ----
        float mx_lo = fmaxf(fmaxf(s[0][0], s[0][1]), fmaxf(s[1][0], s[1][1]));
        mx_lo = fmaxf(mx_lo, fmaxf(fmaxf(s[2][0], s[2][1]), fmaxf(s[3][0], s[3][1])));
        float mx_hi = fmaxf(fmaxf(s[0][2], s[0][3]), fmaxf(s[1][2], s[1][3]));
        mx_hi = fmaxf(mx_hi, fmaxf(fmaxf(s[2][2], s[2][3]), fmaxf(s[3][2], s[3][3])));
        mx_lo = fmaxf(mx_lo, __shfl_xor_sync(0xffffffffu, mx_lo, 1));
        mx_lo = fmaxf(mx_lo, __shfl_xor_sync(0xffffffffu, mx_lo, 2));
        mx_hi = fmaxf(mx_hi, __shfl_xor_sync(0xffffffffu, mx_hi, 1));
        mx_hi = fmaxf(mx_hi, __shfl_xor_sync(0xffffffffu, mx_hi, 2));

        const float mn_lo = fmaxf(m_lo, mx_lo);
        const float mn_hi = fmaxf(m_hi, mx_hi);
        const float sc_lo = __expf(m_lo - mn_lo);
        const float sc_hi = __expf(m_hi - mn_hi);

        // ---- exp + row sums (in registers) ----
        float ps_lo = 0.0f, ps_hi = 0.0f;
#pragma unroll
        for (int nt = 0; nt < 4; nt++) {
            s[nt][0] = __expf(s[nt][0] - mn_lo);
            s[nt][1] = __expf(s[nt][1] - mn_lo);
            s[nt][2] = __expf(s[nt][2] - mn_hi);
            s[nt][3] = __expf(s[nt][3] - mn_hi);
            ps_lo += s[nt][0] + s[nt][1];
            ps_hi += s[nt][2] + s[nt][3];
        }
        ps_lo += __shfl_xor_sync(0xffffffffu, ps_lo, 1);
        ps_lo += __shfl_xor_sync(0xffffffffu, ps_lo, 2);
        ps_hi += __shfl_xor_sync(0xffffffffu, ps_hi, 1);
        ps_hi += __shfl_xor_sync(0xffffffffu, ps_hi, 2);

        l_lo = l_lo * sc_lo + ps_lo;
        l_hi = l_hi * sc_hi + ps_hi;
        m_lo = mn_lo;
        m_hi = mn_hi;

        // rescale accumulators
#pragma unroll
        for (int i = 0; i < 8; i++) {
            acc[i][0] *= sc_lo; acc[i][1] *= sc_lo;
            acc[i][2] *= sc_hi; acc[i][3] *= sc_hi;
        }

        // ---- pack P from S fragments (register-resident, split hi/lo) ----
        uint32_t pah[2][4], pal[2][4];
#pragma unroll
        for (int kc = 0; kc < 2; kc++) {
            split2(s[kc * 2 + 0][0], s[kc * 2 + 0][1], pah[kc][0], pal[kc][0]);
            split2(s[kc * 2 + 0][2], s[kc * 2 + 0][3], pah[kc][1], pal[kc][1]);
            split2(s[kc * 2 + 1][0], s[kc * 2 + 1][1], pah[kc][2], pal[kc][2]);
            split2(s[kc * 2 + 1][2], s[kc * 2 + 1][3], pah[kc][3], pal[kc][3]);
        }

        // ---- acc += P V  (V via ldmatrix.x4.trans; 2 d-groups per load) ----
#pragma unroll
        for (int kc = 0; kc < 2; kc++) {
#pragma unroll
            for (int dp = 0; dp < 4; dp++) {    // d-group pairs: d = dp*16
                uint32_t bhv[4], blv[4];
                ldsm_x4_trans(bhv[0], bhv[1], bhv[2], bhv[3],
                              smem_u32(&Vh[buf][kc * 16 + v_r4][dp * 16 + v_c4]));
                ldsm_x4_trans(blv[0], blv[1], blv[2], blv[3],
                              smem_u32(&Vl[buf][kc * 16 + v_r4][dp * 16 + v_c4]));
                mma_bf16(acc[dp * 2 + 0], pah[kc], bhv + 0);
                mma_bf16(acc[dp * 2 + 0], pah[kc], blv + 0);
                mma_bf16(acc[dp * 2 + 0], pal[kc], bhv + 0);
                mma_bf16(acc[dp * 2 + 1], pah[kc], bhv + 2);
                mma_bf16(acc[dp * 2 + 1], pah[kc], blv + 2);
                mma_bf16(acc[dp * 2 + 1], pal[kc], bhv + 2);
            }
        }
    }

    const float linv_lo = 1.0f / l_lo;
    const float linv_hi = 1.0f / l_hi;

    // write ctx (B,S,512): row q0+r, col h*64 + (nt*8 + ec)
#pragma unroll
    for (int nt = 0; nt < 8; nt++) {
        const int d = nt * 8 + ec;
        float2 o0 = make_float2(acc[nt][0] * linv_lo, acc[nt][1] * linv_lo);
        float2 o1 = make_float2(acc[nt][2] * linv_hi, acc[nt][3] * linv_hi);
        *(float2*)(g_ctx + ((size_t)(b * Sc + q0 + rlo)) * Dc + h * DKc + d) = o0;
        *(float2*)(g_ctx + ((size_t)(b * Sc + q0 + rhi)) * Dc + h * DKc + d) = o1;
    }
}

// ---------------------------------------------------------------------------
extern "C" void kernel_launch(void* const* d_in, const int* in_sizes, int n_in,
                              void* d_out, int out_size)
{
    (void)in_sizes; (void)n_in; (void)out_size;
    const float* key_   = (const float*)d_in[0];
    const float* value_ = (const float*)d_in[1];
    const float* query_ = (const float*)d_in[2];
    const float* m_it   = (const float*)d_in[3];
    const float* m_ist  = (const float*)d_in[4];
    const float* m_df   = (const float*)d_in[5];
    const unsigned char* mask = (const unsigned char*)d_in[6];
    const float* Wq = (const float*)d_in[7];
    const float* bq = (const float*)d_in[8];
    const float* Wk = (const float*)d_in[9];
    const float* bk = (const float*)d_in[10];
    const float* Wv = (const float*)d_in[11];
    const float* bv = (const float*)d_in[12];
    const float* Wo = (const float*)d_in[13];
    const float* bo = (const float*)d_in[14];
    float* out = (float*)d_out;

    void *pqh, *pql, *pkh, *pkl, *pvh, *pvl, *pctx;
    cudaGetSymbolAddress(&pqh, g_qh);
    cudaGetSymbolAddress(&pql, g_ql);
    cudaGetSymbolAddress(&pkh, g_kh);
    cudaGetSymbolAddress(&pkl, g_kl);
    cudaGetSymbolAddress(&pvh, g_vh);
    cudaGetSymbolAddress(&pvl, g_vl);
    cudaGetSymbolAddress(&pctx, g_ctx);

    dim3 gProj(Dc / BNt, (Bc * Sc) / BMt);  // (4, 64)
    mma_gemm<1><<<gProj, 256>>>(query_, Wq, bq, nullptr,
                                (__nv_bfloat16*)pqh, (__nv_bfloat16*)pql, 0.125f);
    mma_gemm<1><<<gProj, 256>>>(key_,   Wk, bk, nullptr,
                                (__nv_bfloat16*)pkh, (__nv_bfloat16*)pkl, 1.0f);
    mma_gemm<1><<<gProj, 256>>>(value_, Wv, bv, nullptr,
                                (__nv_bfloat16*)pvh, (__nv_bfloat16*)pvl, 1.0f);

    attn_mma<<<dim3(Sc / QROWS, Hc, Bc), 256>>>(m_it, m_ist, m_df, mask);

    mma_gemm<0><<<gProj, 256>>>((const float*)pctx, Wo, bo, out,
                                nullptr, nullptr, 1.0f);
}